// round 12
// baseline (speedup 1.0000x reference)
#include <cuda_runtime.h>
#include <cuda_bf16.h>
#include <math.h>
#include <stdint.h>

#define TT     2048
#define HIDD   5120
#define ROPED  64
#define NOPED  128
#define HH     32
#define QKDD   192
#define QLRD   1536
#define DQK    576
#define DLAT   512
#define QBN    6144   // H*QKD
#define ATTN   4096   // H*VDIM
#define SCALE_F 0.07216878364870323f   // 1/sqrt(192)
#define EPS_F  1e-6f

typedef __nv_bfloat16 bf16;

// ----------------------------- f32 scratch -----------------------------------
__device__ float g_qa    [(size_t)TT * QLRD];
__device__ float g_q     [(size_t)TT * QBN];
__device__ float g_lat   [(size_t)TT * DQK];
__device__ float g_k     [(size_t)TT * DQK];
__device__ float g_scores[(size_t)HH * TT * TT];

// --------------------------- bf16 hi/lo scratch -------------------------------
__device__ bf16 g_hsH [(size_t)TT*HIDD],      g_hsL [(size_t)TT*HIDD];
__device__ bf16 g_wqaT_H[(size_t)QLRD*HIDD],  g_wqaT_L[(size_t)QLRD*HIDD];
__device__ bf16 g_qaH [(size_t)TT*QLRD],      g_qaL [(size_t)TT*QLRD];
__device__ bf16 g_wqbT_H[(size_t)QBN*QLRD],   g_wqbT_L[(size_t)QBN*QLRD];
__device__ bf16 g_qH  [(size_t)TT*QBN],       g_qL  [(size_t)TT*QBN];
__device__ bf16 g_wkvaT_H[(size_t)640*HIDD],  g_wkvaT_L[(size_t)640*HIDD];   // padded 576->640
__device__ bf16 g_kH  [(size_t)TT*DQK],       g_kL  [(size_t)TT*DQK];
__device__ bf16 g_vT_H[(size_t)DLAT*TT],      g_vT_L[(size_t)DLAT*TT];
__device__ bf16 g_wkcT_H[(size_t)HH*DLAT*NOPED], g_wkcT_L[(size_t)HH*DLAT*NOPED];
__device__ bf16 g_qinH[(size_t)TT*HH*DQK],    g_qinL[(size_t)TT*HH*DQK];
__device__ bf16 g_scH [(size_t)HH*TT*TT],     g_scL [(size_t)HH*TT*TT];
__device__ bf16 g_ctxH[(size_t)HH*TT*DLAT],   g_ctxL[(size_t)HH*TT*DLAT];
__device__ bf16 g_wvcT_H[(size_t)HH*NOPED*DLAT], g_wvcT_L[(size_t)HH*NOPED*DLAT];
__device__ bf16 g_attH[(size_t)TT*ATTN],      g_attL[(size_t)TT*ATTN];
__device__ bf16 g_woT_H[(size_t)HIDD*ATTN],   g_woT_L[(size_t)HIDD*ATTN];

// ------------------------------ helpers ---------------------------------------
__device__ __forceinline__ uint32_t smem_u32(const void* p) {
    uint32_t a;
    asm("{ .reg .u64 t; cvta.to.shared.u64 t, %1; cvt.u32.u64 %0, t; }" : "=r"(a) : "l"(p));
    return a;
}

#define SWZ64(o) ((o) ^ (((o) >> 3) & 0x30))   // 64B rows (gemm3 tiles)

__device__ __forceinline__ void ldm_x4(uint32_t* r, uint32_t addr) {
    asm volatile("ldmatrix.sync.aligned.m8n8.x4.shared.b16 {%0,%1,%2,%3}, [%4];"
        : "=r"(r[0]), "=r"(r[1]), "=r"(r[2]), "=r"(r[3]) : "r"(addr));
}

__device__ __forceinline__ void mma16816(float* c, const uint32_t* a, const uint32_t* b) {
    asm volatile("mma.sync.aligned.m16n8k16.row.col.f32.bf16.bf16.f32 "
        "{%0,%1,%2,%3}, {%4,%5,%6,%7}, {%8,%9}, {%0,%1,%2,%3};"
        : "+f"(c[0]), "+f"(c[1]), "+f"(c[2]), "+f"(c[3])
        : "r"(a[0]), "r"(a[1]), "r"(a[2]), "r"(a[3]), "r"(b[0]), "r"(b[1]));
}

__device__ __forceinline__ void cpa16(uint32_t dst, const void* src) {
    asm volatile("cp.async.cg.shared.global [%0], [%1], 16;" :: "r"(dst), "l"(src));
}
#define CP_COMMIT() asm volatile("cp.async.commit_group;" ::: "memory")
#define CP_WAIT0()  asm volatile("cp.async.wait_group 0;" ::: "memory")
#define CP_WAIT1()  asm volatile("cp.async.wait_group 1;" ::: "memory")
#define CP_WAIT2()  asm volatile("cp.async.wait_group 2;" ::: "memory")

// ----------------------- warp-MMA 3-term split GEMM ---------------------------
// C[M,N] = A[M,K] * BT[N,K]^T; A/BT bf16 hi/lo, K-contig. 256x128 CTA tile,
// warps 4(M)x2(N) = 64x64 each. 3-stage cp.async ring, K-chunks of 32.
// mode: 0 none, 1 causal-skip (scores), 2 k-limit (pv). M % 256 == 0.
#define T_A_HI 0
#define T_A_LO 16384
#define T_B_HI 32768
#define T_B_LO 40960
#define STG_SZ 49152
#define GSM_DYN (3*STG_SZ + 1024)

__global__ __launch_bounds__(256, 1)
void gemm3(const bf16* __restrict__ AH, const bf16* __restrict__ AL,
           const bf16* __restrict__ BH, const bf16* __restrict__ BL,
           float* __restrict__ C, bf16* __restrict__ OH, bf16* __restrict__ OL,
           int N, int K, int lda, int ldb, int ldc,
           long long sA, long long sB, long long sC, int mode)
{
    const int bm = blockIdx.y * 256, bn = blockIdx.x * 128;
    if (mode == 1 && bn >= bm + 256) return;
    const int kmax = (mode == 2) ? (bm + 256) : K;
    const int nch  = kmax >> 5;

    AH += (long long)blockIdx.z * sA;  AL += (long long)blockIdx.z * sA;
    BH += (long long)blockIdx.z * sB;  BL += (long long)blockIdx.z * sB;

    extern __shared__ char smraw[];
    char* smem = (char*)(((uintptr_t)smraw + 1023) & ~(uintptr_t)1023);
    const uint32_t sb = smem_u32(smem);

    const int tid  = threadIdx.x;
    const int lane = tid & 31, warp = tid >> 5;
    const int wm = (warp >> 1) * 64;     // 4 M-warps
    const int wn = (warp & 1) * 64;      // 2 N-warps

    float acc[4][8][4];
#pragma unroll
    for (int i = 0; i < 4; i++)
#pragma unroll
        for (int j = 0; j < 8; j++)
#pragma unroll
            for (int q = 0; q < 4; q++) acc[i][j][q] = 0.f;

    const int a_row = (lane & 15);
    const int a_kof = (lane & 16) ? 8 : 0;
    const int b_sel = lane >> 3;
    const int b_row = (lane & 7) + ((b_sel & 2) ? 8 : 0);
    const int b_kof = (b_sel & 1) ? 8 : 0;

#define LOAD_CHUNK(ci, stg)                                                     \
    do {                                                                        \
        const uint32_t _st = sb + (uint32_t)(stg) * STG_SZ;                     \
        const int _k0 = (ci) << 5;                                              \
        _Pragma("unroll")                                                       \
        for (int qq = 0; qq < 4; qq++) {                                        \
            int u = tid + qq * 256;                                             \
            int r = u >> 2, cc = u & 3;                                         \
            uint32_t sw = SWZ64((uint32_t)(r * 64 + cc * 16));                  \
            size_t gA = (size_t)(bm + r) * lda + _k0 + cc * 8;                  \
            cpa16(_st + T_A_HI + sw, AH + gA);                                  \
            cpa16(_st + T_A_LO + sw, AL + gA);                                  \
        }                                                                       \
        _Pragma("unroll")                                                       \
        for (int qq = 0; qq < 2; qq++) {                                        \
            int u = tid + qq * 256;                                             \
            int r = u >> 2, cc = u & 3;                                         \
            uint32_t sw = SWZ64((uint32_t)(r * 64 + cc * 16));                  \
            size_t gB = (size_t)(bn + r) * ldb + _k0 + cc * 8;                  \
            cpa16(_st + T_B_HI + sw, BH + gB);                                  \
            cpa16(_st + T_B_LO + sw, BL + gB);                                  \
        }                                                                       \
    } while (0)

    LOAD_CHUNK(0, 0); CP_COMMIT();
    if (nch > 1) { LOAD_CHUNK(1, 1); CP_COMMIT(); }

    int sc_cur = 0, sc_nxt = 2;

    for (int c = 0; c < nch; c++) {
        if (c + 2 < nch) {
            LOAD_CHUNK(c + 2, sc_nxt); CP_COMMIT();
            sc_nxt = (sc_nxt + 1 == 3) ? 0 : sc_nxt + 1;
            CP_WAIT2();
        } else if (c + 1 < nch) {
            CP_WAIT1();
        } else {
            CP_WAIT0();
        }
        __syncthreads();

        const uint32_t st = sb + (uint32_t)sc_cur * STG_SZ;
        sc_cur = (sc_cur + 1 == 3) ? 0 : sc_cur + 1;
#pragma unroll
        for (int kk = 0; kk < 32; kk += 16) {
            uint32_t bh[8][2], bl[8][2];
#pragma unroll
            for (int p = 0; p < 4; p++) {
                uint32_t boff = SWZ64((uint32_t)((wn + p * 16 + b_row) * 64 + (kk + b_kof) * 2));
                uint32_t r[4];
                ldm_x4(r, st + T_B_HI + boff);
                bh[2*p][0] = r[0]; bh[2*p][1] = r[1]; bh[2*p+1][0] = r[2]; bh[2*p+1][1] = r[3];
                ldm_x4(r, st + T_B_LO + boff);
                bl[2*p][0] = r[0]; bl[2*p][1] = r[1]; bl[2*p+1][0] = r[2]; bl[2*p+1][1] = r[3];
            }
#pragma unroll
            for (int mt = 0; mt < 4; mt++) {
                uint32_t aoff = SWZ64((uint32_t)((wm + mt * 16 + a_row) * 64 + (kk + a_kof) * 2));
                uint32_t ah[4], al[4];
                ldm_x4(ah, st + T_A_HI + aoff);
                ldm_x4(al, st + T_A_LO + aoff);
#pragma unroll
                for (int nt = 0; nt < 8; nt++) {
                    mma16816(acc[mt][nt], ah, bh[nt]);
                    mma16816(acc[mt][nt], ah, bl[nt]);
                    mma16816(acc[mt][nt], al, bh[nt]);
                }
            }
        }
        __syncthreads();
    }
#undef LOAD_CHUNK

    // ---- epilogue: f32 and/or bf16 hi/lo ----
#pragma unroll
    for (int mt = 0; mt < 4; mt++) {
#pragma unroll
        for (int nt = 0; nt < 8; nt++) {
            int r = bm + wm + mt * 16 + (lane >> 2);
            int c = bn + wn + nt * 8 + 2 * (lane & 3);
            if (c >= N) continue;
            float v0 = acc[mt][nt][0], v1 = acc[mt][nt][1];
            float v2 = acc[mt][nt][2], v3 = acc[mt][nt][3];
            if (C) {
                float* Cz = C + (long long)blockIdx.z * sC;
                *(float2*)&Cz[(size_t)r * ldc + c]       = make_float2(v0, v1);
                *(float2*)&Cz[(size_t)(r + 8) * ldc + c] = make_float2(v2, v3);
            }
            if (OH) {
                bf16* Hz = OH + (long long)blockIdx.z * sC;
                bf16* Lz = OL + (long long)blockIdx.z * sC;
                bf16 h0 = __float2bfloat16(v0), h1 = __float2bfloat16(v1);
                bf16 h2 = __float2bfloat16(v2), h3 = __float2bfloat16(v3);
                *(__nv_bfloat162*)&Hz[(size_t)r * ldc + c] = __nv_bfloat162(h0, h1);
                *(__nv_bfloat162*)&Hz[(size_t)(r + 8) * ldc + c] = __nv_bfloat162(h2, h3);
                *(__nv_bfloat162*)&Lz[(size_t)r * ldc + c] =
                    __nv_bfloat162(__float2bfloat16(v0 - __bfloat162float(h0)),
                                   __float2bfloat16(v1 - __bfloat162float(h1)));
                *(__nv_bfloat162*)&Lz[(size_t)(r + 8) * ldc + c] =
                    __nv_bfloat162(__float2bfloat16(v2 - __bfloat162float(h2)),
                                   __float2bfloat16(v3 - __bfloat162float(h3)));
            }
        }
    }
}

// --------------------- elementwise f32 -> bf16 hi/lo ---------------------------
__global__ void conv_split(const float* __restrict__ x, bf16* __restrict__ hi,
                           bf16* __restrict__ lo, long long n4)
{
    long long i = (long long)blockIdx.x * blockDim.x + threadIdx.x;
    long long stride = (long long)gridDim.x * blockDim.x;
    for (; i < n4; i += stride) {
        float4 v = ((const float4*)x)[i];
        bf16 hx = __float2bfloat16(v.x), hy = __float2bfloat16(v.y);
        bf16 hz = __float2bfloat16(v.z), hw = __float2bfloat16(v.w);
        __nv_bfloat162* H = (__nv_bfloat162*)hi;
        __nv_bfloat162* L = (__nv_bfloat162*)lo;
        H[2*i]   = __nv_bfloat162(hx, hy);
        H[2*i+1] = __nv_bfloat162(hz, hw);
        L[2*i]   = __nv_bfloat162(__float2bfloat16(v.x - __bfloat162float(hx)),
                                  __float2bfloat16(v.y - __bfloat162float(hy)));
        L[2*i+1] = __nv_bfloat162(__float2bfloat16(v.z - __bfloat162float(hz)),
                                  __float2bfloat16(v.w - __bfloat162float(hw)));
    }
}

// ------------- transpose + split: src[R][C] f32 (lda) -> dst[CP][R] bf16 -------
__global__ void tconv(const float* __restrict__ src, bf16* __restrict__ dh,
                      bf16* __restrict__ dl, int R, int C, int CP, int lda,
                      long long zs, long long zd)
{
    src += (long long)blockIdx.z * zs;
    dh  += (long long)blockIdx.z * zd;
    dl  += (long long)blockIdx.z * zd;
    __shared__ float t[32][33];
    int c  = blockIdx.x * 32 + threadIdx.x;
    int r0 = blockIdx.y * 32;
#pragma unroll
    for (int i = 0; i < 32; i += 8) {
        int r = r0 + threadIdx.y + i;
        t[threadIdx.y + i][threadIdx.x] = (c < C && r < R) ? src[(size_t)r * lda + c] : 0.f;
    }
    __syncthreads();
    int ro = blockIdx.x * 32;
    int co = r0 + threadIdx.x;
#pragma unroll
    for (int i = 0; i < 32; i += 8) {
        int rr = ro + threadIdx.y + i;
        if (rr < CP && co < R) {
            float v = t[threadIdx.x][threadIdx.y + i];
            bf16 h = __float2bfloat16(v);
            dh[(size_t)rr * R + co] = h;
            dl[(size_t)rr * R + co] = __float2bfloat16(v - __bfloat162float(h));
        }
    }
}

// ------------------------- block reduce helper -------------------------------
__device__ __forceinline__ float blockReduce(float v, bool isMax)
{
    __shared__ float sm[9];
    int lane = threadIdx.x & 31, w = threadIdx.x >> 5;
#pragma unroll
    for (int o = 16; o > 0; o >>= 1) {
        float ov = __shfl_xor_sync(0xffffffffu, v, o);
        v = isMax ? fmaxf(v, ov) : v + ov;
    }
    if (lane == 0) sm[w] = v;
    __syncthreads();
    if (w == 0) {
        int nw = blockDim.x >> 5;
        v = (lane < nw) ? sm[lane] : (isMax ? -INFINITY : 0.f);
#pragma unroll
        for (int o = 4; o > 0; o >>= 1) {
            float ov = __shfl_xor_sync(0xffffffffu, v, o);
            v = isMax ? fmaxf(v, ov) : v + ov;
        }
        if (lane == 0) sm[8] = v;
    }
    __syncthreads();
    return sm[8];
}

// -------------- rmsnorm rows, fused split output (hi/lo bf16) -----------------
__global__ void rmsnorm_split(const float* __restrict__ x, const float* __restrict__ w,
                              bf16* __restrict__ oh, bf16* __restrict__ ol, int n)
{
    const float* row = x + (size_t)blockIdx.x * n;
    bf16* rh = oh + (size_t)blockIdx.x * n;
    bf16* rl = ol + (size_t)blockIdx.x * n;
    float s = 0.f;
    for (int i = threadIdx.x; i < n; i += blockDim.x) { float v = row[i]; s += v * v; }
    s = blockReduce(s, false);
    float sc = rsqrtf(s / (float)n + EPS_F);
    for (int i = threadIdx.x; i < n; i += blockDim.x) {
        float v = row[i] * sc * w[i];
        bf16 h = __float2bfloat16(v);
        rh[i] = h;
        rl[i] = __float2bfloat16(v - __bfloat162float(h));
    }
}

__device__ __forceinline__ void rope_cs(int posv, int j, float& c, float& s)
{
    float e    = (float)(2 * j) * (1.0f / 64.0f);
    float invf = 1.0f / powf(10000.0f, e);
    float freq = (float)posv * invf;
    double fd  = (double)freq;
    double q   = floor(fd * 0.15915494309189535);
    double r   = fd - q * 6.283185307179586;
    float  rf  = (float)r;
    c = cosf(rf); s = sinf(rf);
}

__global__ void build_k(const float* __restrict__ lat, const float* __restrict__ w,
                        float* __restrict__ k)
{
    int t = blockIdx.x;
    const float* L = lat + (size_t)t * DQK;
    float*       K = k   + (size_t)t * DQK;
    float ssq = 0.f;
    for (int i = threadIdx.x; i < DLAT; i += blockDim.x) { float v = L[i]; ssq += v * v; }
    ssq = blockReduce(ssq, false);
    float sc = rsqrtf(ssq / (float)DLAT + EPS_F);
    for (int i = threadIdx.x; i < DLAT; i += blockDim.x) K[i] = L[i] * sc * w[i];
    if (threadIdx.x < 32) {
        int j = threadIdx.x;
        float c, s;
        rope_cs(t, j, c, s);
        float x1 = L[DLAT + 2*j], x2 = L[DLAT + 2*j + 1];
        K[DLAT + 2*j]     = x1 * c - x2 * s;
        K[DLAT + 2*j + 1] = x2 * c + x1 * s;
    }
}

// ------------- q-side rope, writing qin hi/lo bf16 directly ------------------
__global__ void rope_q(const float* __restrict__ q, bf16* __restrict__ qh,
                       bf16* __restrict__ ql)
{
    int t = blockIdx.x, h = blockIdx.y, j = threadIdx.x;
    const float* src = q + (size_t)t * QBN + h * QKDD + NOPED;
    size_t off = ((size_t)t * HH + h) * DQK + DLAT;
    float c, s;
    rope_cs(t, j, c, s);
    float x1 = src[2*j], x2 = src[2*j + 1];
    float o1 = x1 * c - x2 * s;
    float o2 = x2 * c + x1 * s;
    bf16 h1 = __float2bfloat16(o1), h2 = __float2bfloat16(o2);
    qh[off + 2*j]     = h1;
    qh[off + 2*j + 1] = h2;
    ql[off + 2*j]     = __float2bfloat16(o1 - __bfloat162float(h1));
    ql[off + 2*j + 1] = __float2bfloat16(o2 - __bfloat162float(h2));
}

// ------- causal softmax fused with bf16 hi/lo split output -------------------
__global__ void softmax_split(const float* __restrict__ scores,
                              bf16* __restrict__ SH, bf16* __restrict__ SL)
{
    int t = blockIdx.x, h = blockIdx.y;
    const float* row = scores + ((size_t)h * TT + t) * TT;
    bf16* oh = SH + ((size_t)h * TT + t) * TT;
    bf16* ol = SL + ((size_t)h * TT + t) * TT;
    int n = t + 1;
    int nlim = ((t >> 8) + 1) << 8;   // 256-aligned extent read by PV gemm (M-tile 256)

    float m = -INFINITY;
    for (int i = threadIdx.x; i < n; i += blockDim.x)
        m = fmaxf(m, row[i] * SCALE_F);
    m = blockReduce(m, true);

    float s = 0.f;
    for (int i = threadIdx.x; i < n; i += blockDim.x)
        s += expf(row[i] * SCALE_F - m);
    s = blockReduce(s, false);
    float inv = 1.f / s;

    for (int i = threadIdx.x; i < nlim; i += blockDim.x) {
        float p = (i < n) ? expf(row[i] * SCALE_F - m) * inv : 0.f;
        bf16 hp = __float2bfloat16(p);
        oh[i] = hp;
        ol[i] = __float2bfloat16(p - __bfloat162float(hp));
    }
}

// ------------------------------- launch --------------------------------------
static inline int cblk(long long n4) {
    long long b = (n4 + 255) / 256;
    return (int)(b > 262144 ? 262144 : b);
}

extern "C" void kernel_launch(void* const* d_in, const int* in_sizes, int n_in,
                              void* d_out, int out_size)
{
    const float* hs       = (const float*)d_in[0];
    const float* w_q_a    = (const float*)d_in[2];
    const float* q_a_ln_w = (const float*)d_in[3];
    const float* w_q_b    = (const float*)d_in[4];
    const float* w_kv_a   = (const float*)d_in[5];
    const float* kv_ln_w  = (const float*)d_in[6];
    const float* w_kc     = (const float*)d_in[7];
    const float* w_vc     = (const float*)d_in[8];
    const float* w_o      = (const float*)d_in[9];
    float*       out      = (float*)d_out;

    float *p_qa, *p_q, *p_lat, *p_k, *p_sc;
    cudaGetSymbolAddress((void**)&p_qa,  g_qa);
    cudaGetSymbolAddress((void**)&p_q,   g_q);
    cudaGetSymbolAddress((void**)&p_lat, g_lat);
    cudaGetSymbolAddress((void**)&p_k,   g_k);
    cudaGetSymbolAddress((void**)&p_sc,  g_scores);

    bf16 *hsH,*hsL,*wqaH,*wqaL,*qaH,*qaL,*wqbH,*wqbL,*qH,*qL,*wkvH,*wkvL,*kH,*kL;
    bf16 *vTH,*vTL,*wkcH,*wkcL,*qinH,*qinL,*scH,*scL,*ctxH,*ctxL,*wvcH,*wvcL,*attH,*attL,*woH,*woL;
    cudaGetSymbolAddress((void**)&hsH, g_hsH);   cudaGetSymbolAddress((void**)&hsL, g_hsL);
    cudaGetSymbolAddress((void**)&wqaH, g_wqaT_H); cudaGetSymbolAddress((void**)&wqaL, g_wqaT_L);
    cudaGetSymbolAddress((void**)&qaH, g_qaH);   cudaGetSymbolAddress((void**)&qaL, g_qaL);
    cudaGetSymbolAddress((void**)&wqbH, g_wqbT_H); cudaGetSymbolAddress((void**)&wqbL, g_wqbT_L);
    cudaGetSymbolAddress((void**)&qH, g_qH);     cudaGetSymbolAddress((void**)&qL, g_qL);
    cudaGetSymbolAddress((void**)&wkvH, g_wkvaT_H); cudaGetSymbolAddress((void**)&wkvL, g_wkvaT_L);
    cudaGetSymbolAddress((void**)&kH, g_kH);     cudaGetSymbolAddress((void**)&kL, g_kL);
    cudaGetSymbolAddress((void**)&vTH, g_vT_H);  cudaGetSymbolAddress((void**)&vTL, g_vT_L);
    cudaGetSymbolAddress((void**)&wkcH, g_wkcT_H); cudaGetSymbolAddress((void**)&wkcL, g_wkcT_L);
    cudaGetSymbolAddress((void**)&qinH, g_qinH); cudaGetSymbolAddress((void**)&qinL, g_qinL);
    cudaGetSymbolAddress((void**)&scH, g_scH);   cudaGetSymbolAddress((void**)&scL, g_scL);
    cudaGetSymbolAddress((void**)&ctxH, g_ctxH); cudaGetSymbolAddress((void**)&ctxL, g_ctxL);
    cudaGetSymbolAddress((void**)&wvcH, g_wvcT_H); cudaGetSymbolAddress((void**)&wvcL, g_wvcT_L);
    cudaGetSymbolAddress((void**)&attH, g_attH); cudaGetSymbolAddress((void**)&attL, g_attL);
    cudaGetSymbolAddress((void**)&woH, g_woT_H); cudaGetSymbolAddress((void**)&woL, g_woT_L);

    cudaFuncSetAttribute(gemm3, cudaFuncAttributeMaxDynamicSharedMemorySize, GSM_DYN);
    const int DS = GSM_DYN;
    dim3 tb(32, 8);

    // --- preprocess weights (transpose + split) ---
    tconv<<<dim3(QLRD/32, HIDD/32), tb>>>(w_q_a, wqaH, wqaL, HIDD, QLRD, QLRD, QLRD, 0, 0);
    tconv<<<dim3(QBN/32,  QLRD/32), tb>>>(w_q_b, wqbH, wqbL, QLRD, QBN, QBN, QBN, 0, 0);
    tconv<<<dim3(640/32,  HIDD/32), tb>>>(w_kv_a, wkvH, wkvL, HIDD, DQK, 640, DQK, 0, 0);
    tconv<<<dim3(DLAT/32, NOPED/32, HH), tb>>>(w_kc, wkcH, wkcL, NOPED, DLAT, DLAT, DLAT,
        (long long)NOPED*DLAT, (long long)DLAT*NOPED);
    tconv<<<dim3(NOPED/32, DLAT/32, HH), tb>>>(w_vc, wvcH, wvcL, DLAT, NOPED, NOPED, NOPED,
        (long long)DLAT*NOPED, (long long)NOPED*DLAT);
    tconv<<<dim3(HIDD/32, ATTN/32), tb>>>(w_o, woH, woL, ATTN, HIDD, HIDD, HIDD, 0, 0);

    // --- pipeline ---   (M-tiles: 2048/256 = 8)
    long long n4 = (long long)TT*HIDD/4;
    conv_split<<<cblk(n4), 256>>>(hs, hsH, hsL, n4);

    // 1) qa = hs @ w_q_a  (f32 out for rmsnorm)
    gemm3<<<dim3(QLRD/128, 8, 1), 256, DS>>>(hsH, hsL, wqaH, wqaL, p_qa, 0, 0,
        QLRD, HIDD, HIDD, HIDD, QLRD, 0, 0, 0, 0);
    // 2) rmsnorm fused split
    rmsnorm_split<<<TT, 256>>>(p_qa, q_a_ln_w, qaH, qaL, QLRD);

    // 3) q = qa @ w_q_b  (f32 for rope_q + hi/lo for the nope gemm A-operand)
    gemm3<<<dim3(QBN/128, 8, 1), 256, DS>>>(qaH, qaL, wqbH, wqbL, p_q, qH, qL,
        QBN, QLRD, QLRD, QLRD, QBN, 0, 0, 0, 0);

    // 4) latent = hs @ w_kv_a (f32)
    gemm3<<<dim3(5, 8, 1), 256, DS>>>(hsH, hsL, wkvH, wkvL, p_lat, 0, 0,
        DQK, HIDD, HIDD, HIDD, DQK, 0, 0, 0, 0);

    // 5) k_input + splits
    build_k<<<TT, 256>>>(p_lat, kv_ln_w, p_k);
    n4 = (long long)TT*DQK/4;
    conv_split<<<cblk(n4), 256>>>(p_k, kH, kL, n4);
    tconv<<<dim3(DLAT/32, TT/32), tb>>>(p_k, vTH, vTL, TT, DLAT, DLAT, DQK, 0, 0);

    // 7) qin nope = q_nope @ w_kc[h] -> hi/lo direct
    gemm3<<<dim3(DLAT/128, 8, HH), 256, DS>>>(qH, qL, wkcH, wkcL, 0, qinH, qinL,
        DLAT, NOPED, QBN, NOPED, HH*DQK,
        (long long)QKDD, (long long)DLAT*NOPED, (long long)DQK, 0);

    // 8) qin rope part -> hi/lo direct
    rope_q<<<dim3(TT, HH), 32>>>(p_q, qinH, qinL);

    // 9) scores (causal-skip) -> f32
    gemm3<<<dim3(16, 8, HH), 256, DS>>>(qinH, qinL, kH, kL, p_sc, 0, 0,
        TT, DQK, HH*DQK, DQK, TT,
        (long long)DQK, 0LL, (long long)TT*TT, 1);

    // 10) softmax fused split -> scH/scL (zero-fill to 256-aligned extent)
    softmax_split<<<dim3(TT, HH), 256>>>(p_sc, scH, scL);

    // 11) ctx = probs @ v (k-limited) -> hi/lo direct
    gemm3<<<dim3(DLAT/128, 8, HH), 256, DS>>>(scH, scL, vTH, vTL, 0, ctxH, ctxL,
        DLAT, TT, TT, TT, DLAT,
        (long long)TT*TT, 0LL, (long long)TT*DLAT, 2);

    // 12) att = ctx @ w_vc[h] -> hi/lo direct
    gemm3<<<dim3(1, 8, HH), 256, DS>>>(ctxH, ctxL, wvcH, wvcL, 0, attH, attL,
        NOPED, DLAT, DLAT, DLAT, ATTN,
        (long long)TT*DLAT, (long long)NOPED*DLAT, (long long)NOPED, 0);

    // 13) out = att @ w_o (f32)
    gemm3<<<dim3(HIDD/128, 8, 1), 256, DS>>>(attH, attL, woH, woL, out, 0, 0,
        HIDD, ATTN, ATTN, ATTN, HIDD, 0, 0, 0, 0);
}

// round 13
// speedup vs baseline: 1.5393x; 1.5393x over previous
#include <cuda_runtime.h>
#include <cuda_bf16.h>
#include <math.h>
#include <stdint.h>

#define TT     2048
#define HIDD   5120
#define ROPED  64
#define NOPED  128
#define HH     32
#define QKDD   192
#define QLRD   1536
#define DQK    576
#define DLAT   512
#define QBN    6144   // H*QKD
#define ATTN   4096   // H*VDIM
#define SCALE_F 0.07216878364870323f   // 1/sqrt(192)
#define EPS_F  1e-6f

typedef __nv_bfloat16 bf16;

// ----------------------------- f32 scratch -----------------------------------
__device__ float g_qa    [(size_t)TT * QLRD];
__device__ float g_q     [(size_t)TT * QBN];
__device__ float g_lat   [(size_t)TT * DQK];
__device__ float g_k     [(size_t)TT * DQK];
__device__ float g_scores[(size_t)HH * TT * TT];

// --------------------------- bf16 hi/lo scratch -------------------------------
__device__ bf16 g_hsH [(size_t)TT*HIDD],      g_hsL [(size_t)TT*HIDD];
__device__ bf16 g_wqaT_H[(size_t)QLRD*HIDD],  g_wqaT_L[(size_t)QLRD*HIDD];
__device__ bf16 g_qaH [(size_t)TT*QLRD],      g_qaL [(size_t)TT*QLRD];
__device__ bf16 g_wqbT_H[(size_t)QBN*QLRD],   g_wqbT_L[(size_t)QBN*QLRD];
__device__ bf16 g_qH  [(size_t)TT*QBN],       g_qL  [(size_t)TT*QBN];   // Q' (pe roped in place)
__device__ bf16 g_wkvaT_H[(size_t)640*HIDD],  g_wkvaT_L[(size_t)640*HIDD];   // padded 576->640
__device__ bf16 g_kH  [(size_t)TT*DQK],       g_kL  [(size_t)TT*DQK];
__device__ bf16 g_wkcH[(size_t)HH*NOPED*DLAT], g_wkcL[(size_t)HH*NOPED*DLAT];  // [h][d][r] K-contig
__device__ bf16 g_kpH [(size_t)HH*TT*QKDD],   g_kpL [(size_t)HH*TT*QKDD];     // K' per head [h][s][192]
__device__ bf16 g_scH [(size_t)HH*TT*TT],     g_scL [(size_t)HH*TT*TT];
__device__ bf16 g_wvcT_H[(size_t)HH*NOPED*DLAT], g_wvcT_L[(size_t)HH*NOPED*DLAT]; // [h][v][r]
__device__ bf16 g_vwH [(size_t)HH*NOPED*TT],  g_vwL [(size_t)HH*NOPED*TT];    // vwT [h][v][s]
__device__ bf16 g_attH[(size_t)TT*ATTN],      g_attL[(size_t)TT*ATTN];
__device__ bf16 g_woT_H[(size_t)HIDD*ATTN],   g_woT_L[(size_t)HIDD*ATTN];

// ------------------------------ helpers ---------------------------------------
__device__ __forceinline__ uint32_t smem_u32(const void* p) {
    uint32_t a;
    asm("{ .reg .u64 t; cvta.to.shared.u64 t, %1; cvt.u32.u64 %0, t; }" : "=r"(a) : "l"(p));
    return a;
}

#define SWZ(o) ((o) ^ (((o) >> 3) & 0x70))

__device__ __forceinline__ void ldm_x4(uint32_t* r, uint32_t addr) {
    asm volatile("ldmatrix.sync.aligned.m8n8.x4.shared.b16 {%0,%1,%2,%3}, [%4];"
        : "=r"(r[0]), "=r"(r[1]), "=r"(r[2]), "=r"(r[3]) : "r"(addr));
}

__device__ __forceinline__ void mma16816(float* c, const uint32_t* a, const uint32_t* b) {
    asm volatile("mma.sync.aligned.m16n8k16.row.col.f32.bf16.bf16.f32 "
        "{%0,%1,%2,%3}, {%4,%5,%6,%7}, {%8,%9}, {%0,%1,%2,%3};"
        : "+f"(c[0]), "+f"(c[1]), "+f"(c[2]), "+f"(c[3])
        : "r"(a[0]), "r"(a[1]), "r"(a[2]), "r"(a[3]), "r"(b[0]), "r"(b[1]));
}

__device__ __forceinline__ void cpa16(uint32_t dst, const void* src) {
    asm volatile("cp.async.cg.shared.global [%0], [%1], 16;" :: "r"(dst), "l"(src));
}
#define CP_COMMIT() asm volatile("cp.async.commit_group;" ::: "memory")
#define CP_WAIT0()  asm volatile("cp.async.wait_group 0;" ::: "memory")
#define CP_WAIT1()  asm volatile("cp.async.wait_group 1;" ::: "memory")

// ----------------------- warp-MMA 3-term split GEMM (R10 config) --------------
// C[M,N] = A[M,K] * BT[N,K]^T; A/BT bf16 hi/lo, K-contig. 128x128 CTA tile,
// 2-stage cp.async over K-chunks of 64. Optional outputs f32 C and/or bf16 OH/OL.
// mode: 0 none, 1 causal-skip, 2 k-limit (pv). M % 128 == 0.
#define T_A_HI 0
#define T_A_LO 16384
#define T_B_HI 32768
#define T_B_LO 49152
#define STG_SZ 65536
#define GSM_DYN (2*STG_SZ + 1024)

__global__ __launch_bounds__(256)
void gemm3(const bf16* __restrict__ AH, const bf16* __restrict__ AL,
           const bf16* __restrict__ BH, const bf16* __restrict__ BL,
           float* __restrict__ C, bf16* __restrict__ OH, bf16* __restrict__ OL,
           int N, int K, int lda, int ldb, int ldc,
           long long sA, long long sB, long long sC, int mode)
{
    const int bm = blockIdx.y * 128, bn = blockIdx.x * 128;
    if (mode == 1 && bn >= bm + 128) return;
    const int kmax = (mode == 2) ? (bm + 128) : K;
    const int nch  = kmax >> 6;

    AH += (long long)blockIdx.z * sA;  AL += (long long)blockIdx.z * sA;
    BH += (long long)blockIdx.z * sB;  BL += (long long)blockIdx.z * sB;

    extern __shared__ char smraw[];
    char* smem = (char*)(((uintptr_t)smraw + 1023) & ~(uintptr_t)1023);
    const uint32_t sb = smem_u32(smem);

    const int tid  = threadIdx.x;
    const int lane = tid & 31, warp = tid >> 5;
    const int wm = (warp >> 2) * 64;
    const int wn = (warp & 3) * 32;

    float acc[4][4][4];
#pragma unroll
    for (int i = 0; i < 4; i++)
#pragma unroll
        for (int j = 0; j < 4; j++)
#pragma unroll
            for (int q = 0; q < 4; q++) acc[i][j][q] = 0.f;

    const int a_row = (lane & 15);
    const int a_kof = (lane & 16) ? 8 : 0;
    const int b_sel = lane >> 3;
    const int b_row = (lane & 7) + ((b_sel & 2) ? 8 : 0);
    const int b_kof = (b_sel & 1) ? 8 : 0;

    const int l_row = tid >> 3, l_c16 = tid & 7;

#define LOAD_CHUNK(ci, stg)                                                      \
    do {                                                                         \
        const uint32_t _st = sb + (uint32_t)(stg) * STG_SZ;                      \
        const int _k0 = (ci) << 6;                                               \
        _Pragma("unroll")                                                        \
        for (int it = 0; it < 4; it++) {                                         \
            int row = l_row + it * 32;                                           \
            uint32_t sw = SWZ((uint32_t)(row * 128 + l_c16 * 16));               \
            size_t gA = (size_t)(bm + row) * lda + _k0 + l_c16 * 8;              \
            size_t gB = (size_t)(bn + row) * ldb + _k0 + l_c16 * 8;              \
            cpa16(_st + T_A_HI + sw, AH + gA);                                   \
            cpa16(_st + T_A_LO + sw, AL + gA);                                   \
            cpa16(_st + T_B_HI + sw, BH + gB);                                   \
            cpa16(_st + T_B_LO + sw, BL + gB);                                   \
        }                                                                        \
    } while (0)

    LOAD_CHUNK(0, 0); CP_COMMIT();

    for (int c = 0; c < nch; c++) {
        if (c + 1 < nch) {
            LOAD_CHUNK(c + 1, (c + 1) & 1); CP_COMMIT();
            CP_WAIT1();
        } else {
            CP_WAIT0();
        }
        __syncthreads();

        const uint32_t st = sb + (uint32_t)(c & 1) * STG_SZ;
#pragma unroll
        for (int kk = 0; kk < 64; kk += 16) {
            uint32_t bh[4][2], bl[4][2];
#pragma unroll
            for (int p = 0; p < 2; p++) {
                uint32_t boff = SWZ((uint32_t)((wn + p * 16 + b_row) * 128 + (kk + b_kof) * 2));
                uint32_t r[4];
                ldm_x4(r, st + T_B_HI + boff);
                bh[2*p][0] = r[0]; bh[2*p][1] = r[1]; bh[2*p+1][0] = r[2]; bh[2*p+1][1] = r[3];
                ldm_x4(r, st + T_B_LO + boff);
                bl[2*p][0] = r[0]; bl[2*p][1] = r[1]; bl[2*p+1][0] = r[2]; bl[2*p+1][1] = r[3];
            }
#pragma unroll
            for (int mt = 0; mt < 4; mt++) {
                uint32_t aoff = SWZ((uint32_t)((wm + mt * 16 + a_row) * 128 + (kk + a_kof) * 2));
                uint32_t ah[4], al[4];
                ldm_x4(ah, st + T_A_HI + aoff);
                ldm_x4(al, st + T_A_LO + aoff);
#pragma unroll
                for (int nt = 0; nt < 4; nt++) {
                    mma16816(acc[mt][nt], ah, bh[nt]);
                    mma16816(acc[mt][nt], ah, bl[nt]);
                    mma16816(acc[mt][nt], al, bh[nt]);
                }
            }
        }
        __syncthreads();
    }
#undef LOAD_CHUNK

    // ---- epilogue: f32 and/or bf16 hi/lo ----
#pragma unroll
    for (int mt = 0; mt < 4; mt++) {
#pragma unroll
        for (int nt = 0; nt < 4; nt++) {
            int r = bm + wm + mt * 16 + (lane >> 2);
            int c = bn + wn + nt * 8 + 2 * (lane & 3);
            if (c >= N) continue;
            float v0 = acc[mt][nt][0], v1 = acc[mt][nt][1];
            float v2 = acc[mt][nt][2], v3 = acc[mt][nt][3];
            if (C) {
                float* Cz = C + (long long)blockIdx.z * sC;
                *(float2*)&Cz[(size_t)r * ldc + c]       = make_float2(v0, v1);
                *(float2*)&Cz[(size_t)(r + 8) * ldc + c] = make_float2(v2, v3);
            }
            if (OH) {
                bf16* Hz = OH + (long long)blockIdx.z * sC;
                bf16* Lz = OL + (long long)blockIdx.z * sC;
                bf16 h0 = __float2bfloat16(v0), h1 = __float2bfloat16(v1);
                bf16 h2 = __float2bfloat16(v2), h3 = __float2bfloat16(v3);
                *(__nv_bfloat162*)&Hz[(size_t)r * ldc + c] = __nv_bfloat162(h0, h1);
                *(__nv_bfloat162*)&Hz[(size_t)(r + 8) * ldc + c] = __nv_bfloat162(h2, h3);
                *(__nv_bfloat162*)&Lz[(size_t)r * ldc + c] =
                    __nv_bfloat162(__float2bfloat16(v0 - __bfloat162float(h0)),
                                   __float2bfloat16(v1 - __bfloat162float(h1)));
                *(__nv_bfloat162*)&Lz[(size_t)(r + 8) * ldc + c] =
                    __nv_bfloat162(__float2bfloat16(v2 - __bfloat162float(h2)),
                                   __float2bfloat16(v3 - __bfloat162float(h3)));
            }
        }
    }
}

// --------------------- elementwise f32 -> bf16 hi/lo ---------------------------
__global__ void conv_split(const float* __restrict__ x, bf16* __restrict__ hi,
                           bf16* __restrict__ lo, long long n4)
{
    long long i = (long long)blockIdx.x * blockDim.x + threadIdx.x;
    long long stride = (long long)gridDim.x * blockDim.x;
    for (; i < n4; i += stride) {
        float4 v = ((const float4*)x)[i];
        bf16 hx = __float2bfloat16(v.x), hy = __float2bfloat16(v.y);
        bf16 hz = __float2bfloat16(v.z), hw = __float2bfloat16(v.w);
        __nv_bfloat162* H = (__nv_bfloat162*)hi;
        __nv_bfloat162* L = (__nv_bfloat162*)lo;
        H[2*i]   = __nv_bfloat162(hx, hy);
        H[2*i+1] = __nv_bfloat162(hz, hw);
        L[2*i]   = __nv_bfloat162(__float2bfloat16(v.x - __bfloat162float(hx)),
                                  __float2bfloat16(v.y - __bfloat162float(hy)));
        L[2*i+1] = __nv_bfloat162(__float2bfloat16(v.z - __bfloat162float(hz)),
                                  __float2bfloat16(v.w - __bfloat162float(hw)));
    }
}

// ------------- transpose + split: src[R][C] f32 (lda) -> dst[CP][R] bf16 -------
__global__ void tconv(const float* __restrict__ src, bf16* __restrict__ dh,
                      bf16* __restrict__ dl, int R, int C, int CP, int lda,
                      long long zs, long long zd)
{
    src += (long long)blockIdx.z * zs;
    dh  += (long long)blockIdx.z * zd;
    dl  += (long long)blockIdx.z * zd;
    __shared__ float t[32][33];
    int c  = blockIdx.x * 32 + threadIdx.x;
    int r0 = blockIdx.y * 32;
#pragma unroll
    for (int i = 0; i < 32; i += 8) {
        int r = r0 + threadIdx.y + i;
        t[threadIdx.y + i][threadIdx.x] = (c < C && r < R) ? src[(size_t)r * lda + c] : 0.f;
    }
    __syncthreads();
    int ro = blockIdx.x * 32;
    int co = r0 + threadIdx.x;
#pragma unroll
    for (int i = 0; i < 32; i += 8) {
        int rr = ro + threadIdx.y + i;
        if (rr < CP && co < R) {
            float v = t[threadIdx.x][threadIdx.y + i];
            bf16 h = __float2bfloat16(v);
            dh[(size_t)rr * R + co] = h;
            dl[(size_t)rr * R + co] = __float2bfloat16(v - __bfloat162float(h));
        }
    }
}

// ------------------------- block reduce helper -------------------------------
__device__ __forceinline__ float blockReduce(float v, bool isMax)
{
    __shared__ float sm[9];
    int lane = threadIdx.x & 31, w = threadIdx.x >> 5;
#pragma unroll
    for (int o = 16; o > 0; o >>= 1) {
        float ov = __shfl_xor_sync(0xffffffffu, v, o);
        v = isMax ? fmaxf(v, ov) : v + ov;
    }
    if (lane == 0) sm[w] = v;
    __syncthreads();
    if (w == 0) {
        int nw = blockDim.x >> 5;
        v = (lane < nw) ? sm[lane] : (isMax ? -INFINITY : 0.f);
#pragma unroll
        for (int o = 4; o > 0; o >>= 1) {
            float ov = __shfl_xor_sync(0xffffffffu, v, o);
            v = isMax ? fmaxf(v, ov) : v + ov;
        }
        if (lane == 0) sm[8] = v;
    }
    __syncthreads();
    return sm[8];
}

// -------------- rmsnorm rows, fused split output (hi/lo bf16) -----------------
__global__ void rmsnorm_split(const float* __restrict__ x, const float* __restrict__ w,
                              bf16* __restrict__ oh, bf16* __restrict__ ol, int n)
{
    const float* row = x + (size_t)blockIdx.x * n;
    bf16* rh = oh + (size_t)blockIdx.x * n;
    bf16* rl = ol + (size_t)blockIdx.x * n;
    float s = 0.f;
    for (int i = threadIdx.x; i < n; i += blockDim.x) { float v = row[i]; s += v * v; }
    s = blockReduce(s, false);
    float sc = rsqrtf(s / (float)n + EPS_F);
    for (int i = threadIdx.x; i < n; i += blockDim.x) {
        float v = row[i] * sc * w[i];
        bf16 h = __float2bfloat16(v);
        rh[i] = h;
        rl[i] = __float2bfloat16(v - __bfloat162float(h));
    }
}

__device__ __forceinline__ void rope_cs(int posv, int j, float& c, float& s)
{
    float e    = (float)(2 * j) * (1.0f / 64.0f);
    float invf = 1.0f / powf(10000.0f, e);
    float freq = (float)posv * invf;
    double fd  = (double)freq;
    double q   = floor(fd * 0.15915494309189535);
    double r   = fd - q * 6.283185307179586;
    float  rf  = (float)r;
    c = cosf(rf); s = sinf(rf);
}

__global__ void build_k(const float* __restrict__ lat, const float* __restrict__ w,
                        float* __restrict__ k)
{
    int t = blockIdx.x;
    const float* L = lat + (size_t)t * DQK;
    float*       K = k   + (size_t)t * DQK;
    float ssq = 0.f;
    for (int i = threadIdx.x; i < DLAT; i += blockDim.x) { float v = L[i]; ssq += v * v; }
    ssq = blockReduce(ssq, false);
    float sc = rsqrtf(ssq / (float)DLAT + EPS_F);
    for (int i = threadIdx.x; i < DLAT; i += blockDim.x) K[i] = L[i] * sc * w[i];
    if (threadIdx.x < 32) {
        int j = threadIdx.x;
        float c, s;
        rope_cs(t, j, c, s);
        float x1 = L[DLAT + 2*j], x2 = L[DLAT + 2*j + 1];
        K[DLAT + 2*j]     = x1 * c - x2 * s;
        K[DLAT + 2*j + 1] = x2 * c + x1 * s;
    }
}

// ---- replicate roped k_pe into every head's K' rows (cols 128..191) ----------
__global__ void pe_fill(const float* __restrict__ k, bf16* __restrict__ kpH,
                        bf16* __restrict__ kpL)
{
    int s = blockIdx.x, j = threadIdx.x;   // 64 threads
    float v = k[(size_t)s * DQK + DLAT + j];
    bf16 h = __float2bfloat16(v);
    bf16 l = __float2bfloat16(v - __bfloat162float(h));
    for (int hh = 0; hh < HH; hh++) {
        size_t o = ((size_t)hh * TT + s) * QKDD + NOPED + j;
        kpH[o] = h;
        kpL[o] = l;
    }
}

// ------------- q-side rope, writing into qH/qL pe slots in place --------------
__global__ void rope_q(const float* __restrict__ q, bf16* __restrict__ qh,
                       bf16* __restrict__ ql)
{
    int t = blockIdx.x, h = blockIdx.y, j = threadIdx.x;
    const float* src = q + (size_t)t * QBN + h * QKDD + NOPED;
    size_t off = (size_t)t * QBN + h * QKDD + NOPED;
    float c, s;
    rope_cs(t, j, c, s);
    float x1 = src[2*j], x2 = src[2*j + 1];
    float o1 = x1 * c - x2 * s;
    float o2 = x2 * c + x1 * s;
    bf16 h1 = __float2bfloat16(o1), h2 = __float2bfloat16(o2);
    qh[off + 2*j]     = h1;
    qh[off + 2*j + 1] = h2;
    ql[off + 2*j]     = __float2bfloat16(o1 - __bfloat162float(h1));
    ql[off + 2*j + 1] = __float2bfloat16(o2 - __bfloat162float(h2));
}

// ------- causal softmax fused with bf16 hi/lo split output -------------------
__global__ void softmax_split(const float* __restrict__ scores,
                              bf16* __restrict__ SH, bf16* __restrict__ SL)
{
    int t = blockIdx.x, h = blockIdx.y;
    const float* row = scores + ((size_t)h * TT + t) * TT;
    bf16* oh = SH + ((size_t)h * TT + t) * TT;
    bf16* ol = SL + ((size_t)h * TT + t) * TT;
    int n = t + 1;
    int nlim = ((t >> 7) + 1) << 7;   // 128-aligned extent read by PV gemm

    float m = -INFINITY;
    for (int i = threadIdx.x; i < n; i += blockDim.x)
        m = fmaxf(m, row[i] * SCALE_F);
    m = blockReduce(m, true);

    float s = 0.f;
    for (int i = threadIdx.x; i < n; i += blockDim.x)
        s += expf(row[i] * SCALE_F - m);
    s = blockReduce(s, false);
    float inv = 1.f / s;

    for (int i = threadIdx.x; i < nlim; i += blockDim.x) {
        float p = (i < n) ? expf(row[i] * SCALE_F - m) * inv : 0.f;
        bf16 hp = __float2bfloat16(p);
        oh[i] = hp;
        ol[i] = __float2bfloat16(p - __bfloat162float(hp));
    }
}

// ------------------------------- launch --------------------------------------
static inline int cblk(long long n4) {
    long long b = (n4 + 255) / 256;
    return (int)(b > 262144 ? 262144 : b);
}

extern "C" void kernel_launch(void* const* d_in, const int* in_sizes, int n_in,
                              void* d_out, int out_size)
{
    const float* hs       = (const float*)d_in[0];
    const float* w_q_a    = (const float*)d_in[2];
    const float* q_a_ln_w = (const float*)d_in[3];
    const float* w_q_b    = (const float*)d_in[4];
    const float* w_kv_a   = (const float*)d_in[5];
    const float* kv_ln_w  = (const float*)d_in[6];
    const float* w_kc     = (const float*)d_in[7];
    const float* w_vc     = (const float*)d_in[8];
    const float* w_o      = (const float*)d_in[9];
    float*       out      = (float*)d_out;

    float *p_qa, *p_q, *p_lat, *p_k, *p_sc;
    cudaGetSymbolAddress((void**)&p_qa,  g_qa);
    cudaGetSymbolAddress((void**)&p_q,   g_q);
    cudaGetSymbolAddress((void**)&p_lat, g_lat);
    cudaGetSymbolAddress((void**)&p_k,   g_k);
    cudaGetSymbolAddress((void**)&p_sc,  g_scores);

    bf16 *hsH,*hsL,*wqaH,*wqaL,*qaH,*qaL,*wqbH,*wqbL,*qH,*qL,*wkvH,*wkvL,*kH,*kL;
    bf16 *wkcH,*wkcL,*kpH,*kpL,*scH,*scL,*wvcH,*wvcL,*vwH,*vwL,*attH,*attL,*woH,*woL;
    cudaGetSymbolAddress((void**)&hsH, g_hsH);   cudaGetSymbolAddress((void**)&hsL, g_hsL);
    cudaGetSymbolAddress((void**)&wqaH, g_wqaT_H); cudaGetSymbolAddress((void**)&wqaL, g_wqaT_L);
    cudaGetSymbolAddress((void**)&qaH, g_qaH);   cudaGetSymbolAddress((void**)&qaL, g_qaL);
    cudaGetSymbolAddress((void**)&wqbH, g_wqbT_H); cudaGetSymbolAddress((void**)&wqbL, g_wqbT_L);
    cudaGetSymbolAddress((void**)&qH, g_qH);     cudaGetSymbolAddress((void**)&qL, g_qL);
    cudaGetSymbolAddress((void**)&wkvH, g_wkvaT_H); cudaGetSymbolAddress((void**)&wkvL, g_wkvaT_L);
    cudaGetSymbolAddress((void**)&kH, g_kH);     cudaGetSymbolAddress((void**)&kL, g_kL);
    cudaGetSymbolAddress((void**)&wkcH, g_wkcH); cudaGetSymbolAddress((void**)&wkcL, g_wkcL);
    cudaGetSymbolAddress((void**)&kpH, g_kpH);   cudaGetSymbolAddress((void**)&kpL, g_kpL);
    cudaGetSymbolAddress((void**)&scH, g_scH);   cudaGetSymbolAddress((void**)&scL, g_scL);
    cudaGetSymbolAddress((void**)&wvcH, g_wvcT_H); cudaGetSymbolAddress((void**)&wvcL, g_wvcT_L);
    cudaGetSymbolAddress((void**)&vwH, g_vwH);   cudaGetSymbolAddress((void**)&vwL, g_vwL);
    cudaGetSymbolAddress((void**)&attH, g_attH); cudaGetSymbolAddress((void**)&attL, g_attL);
    cudaGetSymbolAddress((void**)&woH, g_woT_H); cudaGetSymbolAddress((void**)&woL, g_woT_L);

    cudaFuncSetAttribute(gemm3, cudaFuncAttributeMaxDynamicSharedMemorySize, GSM_DYN);
    const int DS = GSM_DYN;
    dim3 tb(32, 8);

    // --- preprocess weights ---
    tconv<<<dim3(QLRD/32, HIDD/32), tb>>>(w_q_a, wqaH, wqaL, HIDD, QLRD, QLRD, QLRD, 0, 0);
    tconv<<<dim3(QBN/32,  QLRD/32), tb>>>(w_q_b, wqbH, wqbL, QLRD, QBN, QBN, QBN, 0, 0);
    tconv<<<dim3(640/32,  HIDD/32), tb>>>(w_kv_a, wkvH, wkvL, HIDD, DQK, 640, DQK, 0, 0);
    conv_split<<<cblk((long long)HH*NOPED*DLAT/4), 256>>>(w_kc, wkcH, wkcL,
        (long long)HH*NOPED*DLAT/4);                       // [h][d][r] K-contig, no transpose
    tconv<<<dim3(NOPED/32, DLAT/32, HH), tb>>>(w_vc, wvcH, wvcL, DLAT, NOPED, NOPED, NOPED,
        (long long)DLAT*NOPED, (long long)NOPED*DLAT);     // wvcT [h][v][r]
    tconv<<<dim3(HIDD/32, ATTN/32), tb>>>(w_o, woH, woL, ATTN, HIDD, HIDD, HIDD, 0, 0);

    // --- pipeline ---
    long long n4 = (long long)TT*HIDD/4;
    conv_split<<<cblk(n4), 256>>>(hs, hsH, hsL, n4);

    // 1) qa = hs @ w_q_a  (f32 out for rmsnorm)
    gemm3<<<dim3(QLRD/128, 16, 1), 256, DS>>>(hsH, hsL, wqaH, wqaL, p_qa, 0, 0,
        QLRD, HIDD, HIDD, HIDD, QLRD, 0, 0, 0, 0);
    // 2) rmsnorm fused split
    rmsnorm_split<<<TT, 256>>>(p_qa, q_a_ln_w, qaH, qaL, QLRD);

    // 3) q = qa @ w_q_b  (f32 for rope_q + hi/lo = Q' nope cols)
    gemm3<<<dim3(QBN/128, 16, 1), 256, DS>>>(qaH, qaL, wqbH, wqbL, p_q, qH, qL,
        QBN, QLRD, QLRD, QLRD, QBN, 0, 0, 0, 0);

    // 4) latent = hs @ w_kv_a (f32)
    gemm3<<<dim3(5, 16, 1), 256, DS>>>(hsH, hsL, wkvH, wkvL, p_lat, 0, 0,
        DQK, HIDD, HIDD, HIDD, DQK, 0, 0, 0, 0);

    // 5) k_input (f32) + hi/lo split
    build_k<<<TT, 256>>>(p_lat, kv_ln_w, p_k);
    n4 = (long long)TT*DQK/4;
    conv_split<<<cblk(n4), 256>>>(p_k, kH, kL, n4);

    // 6) kproj[h] = v_norm @ w_kc[h]^T -> K'[h][s][0:128] hi/lo
    gemm3<<<dim3(1, 16, HH), 256, DS>>>(kH, kL, wkcH, wkcL, 0, kpH, kpL,
        NOPED, DLAT, DQK, DLAT, QKDD,
        0LL, (long long)NOPED*DLAT, (long long)TT*QKDD, 0);
    // 7) K'[h][s][128:192] = roped k_pe (all heads)
    pe_fill<<<TT, 64>>>(p_k, kpH, kpL);

    // 8) Q' pe cols: rope into qH/qL in place
    rope_q<<<dim3(TT, HH), 32>>>(p_q, qH, qL);

    // 9) vwT[h] = wvcT[h] @ v_norm^T  (M=128, N=2048, K=512) -> hi/lo
    gemm3<<<dim3(16, 1, HH), 256, DS>>>(wvcH, wvcL, kH, kL, 0, vwH, vwL,
        TT, DLAT, DLAT, DQK, TT,
        (long long)NOPED*DLAT, 0LL, (long long)NOPED*TT, 0);

    // 10) scores[h] = Q'[h] @ K'[h]^T  (K=192, causal-skip) -> f32
    gemm3<<<dim3(16, 16, HH), 256, DS>>>(qH, qL, kpH, kpL, p_sc, 0, 0,
        TT, QKDD, QBN, QKDD, TT,
        (long long)QKDD, (long long)TT*QKDD, (long long)TT*TT, 1);

    // 11) softmax fused split -> scH/scL
    softmax_split<<<dim3(TT, HH), 256>>>(p_sc, scH, scL);

    // 12) att[:, h*128:(h+1)*128] = probs[h] @ vwT[h]^T  (k-limited) -> hi/lo
    gemm3<<<dim3(1, 16, HH), 256, DS>>>(scH, scL, vwH, vwL, 0, attH, attL,
        NOPED, TT, TT, TT, ATTN,
        (long long)TT*TT, (long long)NOPED*TT, 128LL, 2);

    // 13) out = att @ w_o (f32)
    gemm3<<<dim3(HIDD/128, 16, 1), 256, DS>>>(attH, attL, woH, woL, out, 0, 0,
        HIDD, ATTN, ATTN, ATTN, HIDD, 0, 0, 0, 0);
}

// round 14
// speedup vs baseline: 1.6203x; 1.0526x over previous
#include <cuda_runtime.h>
#include <cuda_bf16.h>
#include <math.h>
#include <stdint.h>

#define TT     2048
#define HIDD   5120
#define ROPED  64
#define NOPED  128
#define HH     32
#define QKDD   192
#define QLRD   1536
#define DQK    576
#define DLAT   512
#define QBN    6144   // H*QKD
#define ATTN   4096   // H*VDIM
#define NCOMB  2176   // QLRD + 640 (padded kv cols)
#define SCALE_F 0.07216878364870323f   // 1/sqrt(192)
#define EPS_F  1e-6f

typedef __nv_bfloat16 bf16;

// ----------------------------- f32 scratch -----------------------------------
__device__ float g_qakv  [(size_t)TT * NCOMB];   // [qa(1536) | latent(576) | pad(64)]
__device__ float g_q     [(size_t)TT * QBN];
__device__ float g_k     [(size_t)TT * DQK];
__device__ float g_scores[(size_t)HH * TT * TT];

// --------------------------- bf16 hi/lo scratch -------------------------------
__device__ bf16 g_hsH [(size_t)TT*HIDD],      g_hsL [(size_t)TT*HIDD];
__device__ bf16 g_wcombH[(size_t)NCOMB*HIDD], g_wcombL[(size_t)NCOMB*HIDD];  // [wqaT | wkvaT(640)]
__device__ bf16 g_qaH [(size_t)TT*QLRD],      g_qaL [(size_t)TT*QLRD];
__device__ bf16 g_wqbT_H[(size_t)QBN*QLRD],   g_wqbT_L[(size_t)QBN*QLRD];
__device__ bf16 g_qH  [(size_t)TT*QBN],       g_qL  [(size_t)TT*QBN];   // Q' (pe roped in place)
__device__ bf16 g_kH  [(size_t)TT*DQK],       g_kL  [(size_t)TT*DQK];
__device__ bf16 g_wkcH[(size_t)HH*NOPED*DLAT], g_wkcL[(size_t)HH*NOPED*DLAT];  // [h][d][r] K-contig
__device__ bf16 g_kpH [(size_t)HH*TT*QKDD],   g_kpL [(size_t)HH*TT*QKDD];     // K' per head [h][s][192]
__device__ bf16 g_scH [(size_t)HH*TT*TT],     g_scL [(size_t)HH*TT*TT];
__device__ bf16 g_wvcT_H[(size_t)HH*NOPED*DLAT], g_wvcT_L[(size_t)HH*NOPED*DLAT]; // [h][v][r]
__device__ bf16 g_vwH [(size_t)HH*NOPED*TT],  g_vwL [(size_t)HH*NOPED*TT];    // vwT [h][v][s]
__device__ bf16 g_attH[(size_t)TT*ATTN],      g_attL[(size_t)TT*ATTN];
__device__ bf16 g_woT_H[(size_t)HIDD*ATTN],   g_woT_L[(size_t)HIDD*ATTN];

// ------------------------------ helpers ---------------------------------------
__device__ __forceinline__ uint32_t smem_u32(const void* p) {
    uint32_t a;
    asm("{ .reg .u64 t; cvta.to.shared.u64 t, %1; cvt.u32.u64 %0, t; }" : "=r"(a) : "l"(p));
    return a;
}

#define SWZ(o) ((o) ^ (((o) >> 3) & 0x70))

__device__ __forceinline__ void ldm_x4(uint32_t* r, uint32_t addr) {
    asm volatile("ldmatrix.sync.aligned.m8n8.x4.shared.b16 {%0,%1,%2,%3}, [%4];"
        : "=r"(r[0]), "=r"(r[1]), "=r"(r[2]), "=r"(r[3]) : "r"(addr));
}

__device__ __forceinline__ void mma16816(float* c, const uint32_t* a, const uint32_t* b) {
    asm volatile("mma.sync.aligned.m16n8k16.row.col.f32.bf16.bf16.f32 "
        "{%0,%1,%2,%3}, {%4,%5,%6,%7}, {%8,%9}, {%0,%1,%2,%3};"
        : "+f"(c[0]), "+f"(c[1]), "+f"(c[2]), "+f"(c[3])
        : "r"(a[0]), "r"(a[1]), "r"(a[2]), "r"(a[3]), "r"(b[0]), "r"(b[1]));
}

__device__ __forceinline__ void cpa16(uint32_t dst, const void* src) {
    asm volatile("cp.async.cg.shared.global [%0], [%1], 16;" :: "r"(dst), "l"(src));
}
#define CP_COMMIT() asm volatile("cp.async.commit_group;" ::: "memory")
#define CP_WAIT0()  asm volatile("cp.async.wait_group 0;" ::: "memory")
#define CP_WAIT1()  asm volatile("cp.async.wait_group 1;" ::: "memory")

// ----------------------- warp-MMA 3-term split GEMM ---------------------------
// C[M,N] = A[M,K] * BT[N,K]^T; A/BT bf16 hi/lo, K-contig. 128x128 CTA tile,
// 2-stage cp.async over K-chunks of 64. Term-major MMA issue (RAW distance 16).
// mode: 0 none, 1 causal-skip, 2 k-limit (pv). M % 128 == 0.
#define T_A_HI 0
#define T_A_LO 16384
#define T_B_HI 32768
#define T_B_LO 49152
#define STG_SZ 65536
#define GSM_DYN (2*STG_SZ + 1024)

__global__ __launch_bounds__(256)
void gemm3(const bf16* __restrict__ AH, const bf16* __restrict__ AL,
           const bf16* __restrict__ BH, const bf16* __restrict__ BL,
           float* __restrict__ C, bf16* __restrict__ OH, bf16* __restrict__ OL,
           int N, int K, int lda, int ldb, int ldc,
           long long sA, long long sB, long long sC, int mode)
{
    const int bm = blockIdx.y * 128, bn = blockIdx.x * 128;
    if (mode == 1 && bn >= bm + 128) return;
    const int kmax = (mode == 2) ? (bm + 128) : K;
    const int nch  = kmax >> 6;

    AH += (long long)blockIdx.z * sA;  AL += (long long)blockIdx.z * sA;
    BH += (long long)blockIdx.z * sB;  BL += (long long)blockIdx.z * sB;

    extern __shared__ char smraw[];
    char* smem = (char*)(((uintptr_t)smraw + 1023) & ~(uintptr_t)1023);
    const uint32_t sb = smem_u32(smem);

    const int tid  = threadIdx.x;
    const int lane = tid & 31, warp = tid >> 5;
    const int wm = (warp >> 2) * 64;
    const int wn = (warp & 3) * 32;

    float acc[4][4][4];
#pragma unroll
    for (int i = 0; i < 4; i++)
#pragma unroll
        for (int j = 0; j < 4; j++)
#pragma unroll
            for (int q = 0; q < 4; q++) acc[i][j][q] = 0.f;

    const int a_row = (lane & 15);
    const int a_kof = (lane & 16) ? 8 : 0;
    const int b_sel = lane >> 3;
    const int b_row = (lane & 7) + ((b_sel & 2) ? 8 : 0);
    const int b_kof = (b_sel & 1) ? 8 : 0;

    const int l_row = tid >> 3, l_c16 = tid & 7;

#define LOAD_CHUNK(ci, stg)                                                      \
    do {                                                                         \
        const uint32_t _st = sb + (uint32_t)(stg) * STG_SZ;                      \
        const int _k0 = (ci) << 6;                                               \
        _Pragma("unroll")                                                        \
        for (int it = 0; it < 4; it++) {                                         \
            int row = l_row + it * 32;                                           \
            uint32_t sw = SWZ((uint32_t)(row * 128 + l_c16 * 16));               \
            size_t gA = (size_t)(bm + row) * lda + _k0 + l_c16 * 8;              \
            size_t gB = (size_t)(bn + row) * ldb + _k0 + l_c16 * 8;              \
            cpa16(_st + T_A_HI + sw, AH + gA);                                   \
            cpa16(_st + T_A_LO + sw, AL + gA);                                   \
            cpa16(_st + T_B_HI + sw, BH + gB);                                   \
            cpa16(_st + T_B_LO + sw, BL + gB);                                   \
        }                                                                        \
    } while (0)

    LOAD_CHUNK(0, 0); CP_COMMIT();

    for (int c = 0; c < nch; c++) {
        if (c + 1 < nch) {
            LOAD_CHUNK(c + 1, (c + 1) & 1); CP_COMMIT();
            CP_WAIT1();
        } else {
            CP_WAIT0();
        }
        __syncthreads();

        const uint32_t st = sb + (uint32_t)(c & 1) * STG_SZ;
#pragma unroll
        for (int kk = 0; kk < 64; kk += 16) {
            uint32_t bh[4][2], bl[4][2];
#pragma unroll
            for (int p = 0; p < 2; p++) {
                uint32_t boff = SWZ((uint32_t)((wn + p * 16 + b_row) * 128 + (kk + b_kof) * 2));
                uint32_t r[4];
                ldm_x4(r, st + T_B_HI + boff);
                bh[2*p][0] = r[0]; bh[2*p][1] = r[1]; bh[2*p+1][0] = r[2]; bh[2*p+1][1] = r[3];
                ldm_x4(r, st + T_B_LO + boff);
                bl[2*p][0] = r[0]; bl[2*p][1] = r[1]; bl[2*p+1][0] = r[2]; bl[2*p+1][1] = r[3];
            }
            uint32_t ah[4][4], al[4][4];
#pragma unroll
            for (int mt = 0; mt < 4; mt++) {
                uint32_t aoff = SWZ((uint32_t)((wm + mt * 16 + a_row) * 128 + (kk + a_kof) * 2));
                ldm_x4(ah[mt], st + T_A_HI + aoff);
                ldm_x4(al[mt], st + T_A_LO + aoff);
            }
            // term-major: same-accumulator reuse distance = 16 MMAs
#pragma unroll
            for (int mt = 0; mt < 4; mt++)
#pragma unroll
                for (int nt = 0; nt < 4; nt++)
                    mma16816(acc[mt][nt], ah[mt], bh[nt]);
#pragma unroll
            for (int mt = 0; mt < 4; mt++)
#pragma unroll
                for (int nt = 0; nt < 4; nt++)
                    mma16816(acc[mt][nt], ah[mt], bl[nt]);
#pragma unroll
            for (int mt = 0; mt < 4; mt++)
#pragma unroll
                for (int nt = 0; nt < 4; nt++)
                    mma16816(acc[mt][nt], al[mt], bh[nt]);
        }
        __syncthreads();
    }
#undef LOAD_CHUNK

    // ---- epilogue: f32 and/or bf16 hi/lo ----
#pragma unroll
    for (int mt = 0; mt < 4; mt++) {
#pragma unroll
        for (int nt = 0; nt < 4; nt++) {
            int r = bm + wm + mt * 16 + (lane >> 2);
            int c = bn + wn + nt * 8 + 2 * (lane & 3);
            if (c >= N) continue;
            float v0 = acc[mt][nt][0], v1 = acc[mt][nt][1];
            float v2 = acc[mt][nt][2], v3 = acc[mt][nt][3];
            if (C) {
                float* Cz = C + (long long)blockIdx.z * sC;
                *(float2*)&Cz[(size_t)r * ldc + c]       = make_float2(v0, v1);
                *(float2*)&Cz[(size_t)(r + 8) * ldc + c] = make_float2(v2, v3);
            }
            if (OH) {
                bf16* Hz = OH + (long long)blockIdx.z * sC;
                bf16* Lz = OL + (long long)blockIdx.z * sC;
                bf16 h0 = __float2bfloat16(v0), h1 = __float2bfloat16(v1);
                bf16 h2 = __float2bfloat16(v2), h3 = __float2bfloat16(v3);
                *(__nv_bfloat162*)&Hz[(size_t)r * ldc + c] = __nv_bfloat162(h0, h1);
                *(__nv_bfloat162*)&Hz[(size_t)(r + 8) * ldc + c] = __nv_bfloat162(h2, h3);
                *(__nv_bfloat162*)&Lz[(size_t)r * ldc + c] =
                    __nv_bfloat162(__float2bfloat16(v0 - __bfloat162float(h0)),
                                   __float2bfloat16(v1 - __bfloat162float(h1)));
                *(__nv_bfloat162*)&Lz[(size_t)(r + 8) * ldc + c] =
                    __nv_bfloat162(__float2bfloat16(v2 - __bfloat162float(h2)),
                                   __float2bfloat16(v3 - __bfloat162float(h3)));
            }
        }
    }
}

// --------------------- elementwise f32 -> bf16 hi/lo ---------------------------
__global__ void conv_split(const float* __restrict__ x, bf16* __restrict__ hi,
                           bf16* __restrict__ lo, long long n4)
{
    long long i = (long long)blockIdx.x * blockDim.x + threadIdx.x;
    long long stride = (long long)gridDim.x * blockDim.x;
    for (; i < n4; i += stride) {
        float4 v = ((const float4*)x)[i];
        bf16 hx = __float2bfloat16(v.x), hy = __float2bfloat16(v.y);
        bf16 hz = __float2bfloat16(v.z), hw = __float2bfloat16(v.w);
        __nv_bfloat162* H = (__nv_bfloat162*)hi;
        __nv_bfloat162* L = (__nv_bfloat162*)lo;
        H[2*i]   = __nv_bfloat162(hx, hy);
        H[2*i+1] = __nv_bfloat162(hz, hw);
        L[2*i]   = __nv_bfloat162(__float2bfloat16(v.x - __bfloat162float(hx)),
                                  __float2bfloat16(v.y - __bfloat162float(hy)));
        L[2*i+1] = __nv_bfloat162(__float2bfloat16(v.z - __bfloat162float(hz)),
                                  __float2bfloat16(v.w - __bfloat162float(hw)));
    }
}

// ------------- transpose + split: src[R][C] f32 (lda) -> dst[CP][R] bf16 -------
__global__ void tconv(const float* __restrict__ src, bf16* __restrict__ dh,
                      bf16* __restrict__ dl, int R, int C, int CP, int lda,
                      long long zs, long long zd)
{
    src += (long long)blockIdx.z * zs;
    dh  += (long long)blockIdx.z * zd;
    dl  += (long long)blockIdx.z * zd;
    __shared__ float t[32][33];
    int c  = blockIdx.x * 32 + threadIdx.x;
    int r0 = blockIdx.y * 32;
#pragma unroll
    for (int i = 0; i < 32; i += 8) {
        int r = r0 + threadIdx.y + i;
        t[threadIdx.y + i][threadIdx.x] = (c < C && r < R) ? src[(size_t)r * lda + c] : 0.f;
    }
    __syncthreads();
    int ro = blockIdx.x * 32;
    int co = r0 + threadIdx.x;
#pragma unroll
    for (int i = 0; i < 32; i += 8) {
        int rr = ro + threadIdx.y + i;
        if (rr < CP && co < R) {
            float v = t[threadIdx.x][threadIdx.y + i];
            bf16 h = __float2bfloat16(v);
            dh[(size_t)rr * R + co] = h;
            dl[(size_t)rr * R + co] = __float2bfloat16(v - __bfloat162float(h));
        }
    }
}

// ------------------------- block reduce helper -------------------------------
__device__ __forceinline__ float blockReduce(float v, bool isMax)
{
    __shared__ float sm[9];
    int lane = threadIdx.x & 31, w = threadIdx.x >> 5;
#pragma unroll
    for (int o = 16; o > 0; o >>= 1) {
        float ov = __shfl_xor_sync(0xffffffffu, v, o);
        v = isMax ? fmaxf(v, ov) : v + ov;
    }
    if (lane == 0) sm[w] = v;
    __syncthreads();
    if (w == 0) {
        int nw = blockDim.x >> 5;
        v = (lane < nw) ? sm[lane] : (isMax ? -INFINITY : 0.f);
#pragma unroll
        for (int o = 4; o > 0; o >>= 1) {
            float ov = __shfl_xor_sync(0xffffffffu, v, o);
            v = isMax ? fmaxf(v, ov) : v + ov;
        }
        if (lane == 0) sm[8] = v;
    }
    __syncthreads();
    return sm[8];
}

// ---- rmsnorm rows (row stride ld), fused split output (hi/lo bf16) -----------
__global__ void rmsnorm_split(const float* __restrict__ x, const float* __restrict__ w,
                              bf16* __restrict__ oh, bf16* __restrict__ ol, int n, int ld)
{
    const float* row = x + (size_t)blockIdx.x * ld;
    bf16* rh = oh + (size_t)blockIdx.x * n;
    bf16* rl = ol + (size_t)blockIdx.x * n;
    float s = 0.f;
    for (int i = threadIdx.x; i < n; i += blockDim.x) { float v = row[i]; s += v * v; }
    s = blockReduce(s, false);
    float sc = rsqrtf(s / (float)n + EPS_F);
    for (int i = threadIdx.x; i < n; i += blockDim.x) {
        float v = row[i] * sc * w[i];
        bf16 h = __float2bfloat16(v);
        rh[i] = h;
        rl[i] = __float2bfloat16(v - __bfloat162float(h));
    }
}

__device__ __forceinline__ void rope_cs(int posv, int j, float& c, float& s)
{
    float e    = (float)(2 * j) * (1.0f / 64.0f);
    float invf = 1.0f / powf(10000.0f, e);
    float freq = (float)posv * invf;
    double fd  = (double)freq;
    double q   = floor(fd * 0.15915494309189535);
    double r   = fd - q * 6.283185307179586;
    float  rf  = (float)r;
    c = cosf(rf); s = sinf(rf);
}

// ------- build k_input from latent slice (row stride ldlat) -------------------
__global__ void build_k(const float* __restrict__ lat, int ldlat,
                        const float* __restrict__ w, float* __restrict__ k)
{
    int t = blockIdx.x;
    const float* L = lat + (size_t)t * ldlat;
    float*       K = k   + (size_t)t * DQK;
    float ssq = 0.f;
    for (int i = threadIdx.x; i < DLAT; i += blockDim.x) { float v = L[i]; ssq += v * v; }
    ssq = blockReduce(ssq, false);
    float sc = rsqrtf(ssq / (float)DLAT + EPS_F);
    for (int i = threadIdx.x; i < DLAT; i += blockDim.x) K[i] = L[i] * sc * w[i];
    if (threadIdx.x < 32) {
        int j = threadIdx.x;
        float c, s;
        rope_cs(t, j, c, s);
        float x1 = L[DLAT + 2*j], x2 = L[DLAT + 2*j + 1];
        K[DLAT + 2*j]     = x1 * c - x2 * s;
        K[DLAT + 2*j + 1] = x2 * c + x1 * s;
    }
}

// ---- replicate roped k_pe into every head's K' rows (coalesced) --------------
__global__ void pe_fill(const float* __restrict__ k, bf16* __restrict__ kpH,
                        bf16* __restrict__ kpL)
{
    int s = blockIdx.x, hh = blockIdx.y, j = threadIdx.x;   // 64 threads
    float v = k[(size_t)s * DQK + DLAT + j];
    bf16 h = __float2bfloat16(v);
    bf16 l = __float2bfloat16(v - __bfloat162float(h));
    size_t o = ((size_t)hh * TT + s) * QKDD + NOPED + j;
    kpH[o] = h;
    kpL[o] = l;
}

// ------------- q-side rope, writing into qH/qL pe slots in place --------------
__global__ void rope_q(const float* __restrict__ q, bf16* __restrict__ qh,
                       bf16* __restrict__ ql)
{
    int t = blockIdx.x, h = blockIdx.y, j = threadIdx.x;
    const float* src = q + (size_t)t * QBN + h * QKDD + NOPED;
    size_t off = (size_t)t * QBN + h * QKDD + NOPED;
    float c, s;
    rope_cs(t, j, c, s);
    float x1 = src[2*j], x2 = src[2*j + 1];
    float o1 = x1 * c - x2 * s;
    float o2 = x2 * c + x1 * s;
    bf16 h1 = __float2bfloat16(o1), h2 = __float2bfloat16(o2);
    qh[off + 2*j]     = h1;
    qh[off + 2*j + 1] = h2;
    ql[off + 2*j]     = __float2bfloat16(o1 - __bfloat162float(h1));
    ql[off + 2*j + 1] = __float2bfloat16(o2 - __bfloat162float(h2));
}

// ------- causal softmax fused with bf16 hi/lo split output -------------------
__global__ void softmax_split(const float* __restrict__ scores,
                              bf16* __restrict__ SH, bf16* __restrict__ SL)
{
    int t = blockIdx.x, h = blockIdx.y;
    const float* row = scores + ((size_t)h * TT + t) * TT;
    bf16* oh = SH + ((size_t)h * TT + t) * TT;
    bf16* ol = SL + ((size_t)h * TT + t) * TT;
    int n = t + 1;
    int nlim = ((t >> 7) + 1) << 7;   // 128-aligned extent read by PV gemm

    float m = -INFINITY;
    for (int i = threadIdx.x; i < n; i += blockDim.x)
        m = fmaxf(m, row[i] * SCALE_F);
    m = blockReduce(m, true);

    float s = 0.f;
    for (int i = threadIdx.x; i < n; i += blockDim.x)
        s += expf(row[i] * SCALE_F - m);
    s = blockReduce(s, false);
    float inv = 1.f / s;

    for (int i = threadIdx.x; i < nlim; i += blockDim.x) {
        float p = (i < n) ? expf(row[i] * SCALE_F - m) * inv : 0.f;
        bf16 hp = __float2bfloat16(p);
        oh[i] = hp;
        ol[i] = __float2bfloat16(p - __bfloat162float(hp));
    }
}

// ------------------------------- launch --------------------------------------
static inline int cblk(long long n4) {
    long long b = (n4 + 255) / 256;
    return (int)(b > 262144 ? 262144 : b);
}

extern "C" void kernel_launch(void* const* d_in, const int* in_sizes, int n_in,
                              void* d_out, int out_size)
{
    const float* hs       = (const float*)d_in[0];
    const float* w_q_a    = (const float*)d_in[2];
    const float* q_a_ln_w = (const float*)d_in[3];
    const float* w_q_b    = (const float*)d_in[4];
    const float* w_kv_a   = (const float*)d_in[5];
    const float* kv_ln_w  = (const float*)d_in[6];
    const float* w_kc     = (const float*)d_in[7];
    const float* w_vc     = (const float*)d_in[8];
    const float* w_o      = (const float*)d_in[9];
    float*       out      = (float*)d_out;

    float *p_qakv, *p_q, *p_k, *p_sc;
    cudaGetSymbolAddress((void**)&p_qakv, g_qakv);
    cudaGetSymbolAddress((void**)&p_q,   g_q);
    cudaGetSymbolAddress((void**)&p_k,   g_k);
    cudaGetSymbolAddress((void**)&p_sc,  g_scores);

    bf16 *hsH,*hsL,*wcH,*wcL,*qaH,*qaL,*wqbH,*wqbL,*qH,*qL,*kH,*kL;
    bf16 *wkcH,*wkcL,*kpH,*kpL,*scH,*scL,*wvcH,*wvcL,*vwH,*vwL,*attH,*attL,*woH,*woL;
    cudaGetSymbolAddress((void**)&hsH, g_hsH);   cudaGetSymbolAddress((void**)&hsL, g_hsL);
    cudaGetSymbolAddress((void**)&wcH, g_wcombH); cudaGetSymbolAddress((void**)&wcL, g_wcombL);
    cudaGetSymbolAddress((void**)&qaH, g_qaH);   cudaGetSymbolAddress((void**)&qaL, g_qaL);
    cudaGetSymbolAddress((void**)&wqbH, g_wqbT_H); cudaGetSymbolAddress((void**)&wqbL, g_wqbT_L);
    cudaGetSymbolAddress((void**)&qH, g_qH);     cudaGetSymbolAddress((void**)&qL, g_qL);
    cudaGetSymbolAddress((void**)&kH, g_kH);     cudaGetSymbolAddress((void**)&kL, g_kL);
    cudaGetSymbolAddress((void**)&wkcH, g_wkcH); cudaGetSymbolAddress((void**)&wkcL, g_wkcL);
    cudaGetSymbolAddress((void**)&kpH, g_kpH);   cudaGetSymbolAddress((void**)&kpL, g_kpL);
    cudaGetSymbolAddress((void**)&scH, g_scH);   cudaGetSymbolAddress((void**)&scL, g_scL);
    cudaGetSymbolAddress((void**)&wvcH, g_wvcT_H); cudaGetSymbolAddress((void**)&wvcL, g_wvcT_L);
    cudaGetSymbolAddress((void**)&vwH, g_vwH);   cudaGetSymbolAddress((void**)&vwL, g_vwL);
    cudaGetSymbolAddress((void**)&attH, g_attH); cudaGetSymbolAddress((void**)&attL, g_attL);
    cudaGetSymbolAddress((void**)&woH, g_woT_H); cudaGetSymbolAddress((void**)&woL, g_woT_L);

    cudaFuncSetAttribute(gemm3, cudaFuncAttributeMaxDynamicSharedMemorySize, GSM_DYN);
    const int DS = GSM_DYN;
    dim3 tb(32, 8);

    // --- preprocess weights ---
    // combined [wqaT(1536) | wkvaT(640, zero-padded)] rows, width HIDD
    tconv<<<dim3(QLRD/32, HIDD/32), tb>>>(w_q_a, wcH, wcL, HIDD, QLRD, QLRD, QLRD, 0, 0);
    tconv<<<dim3(640/32,  HIDD/32), tb>>>(w_kv_a,
        wcH + (size_t)QLRD*HIDD, wcL + (size_t)QLRD*HIDD, HIDD, DQK, 640, DQK, 0, 0);
    tconv<<<dim3(QBN/32,  QLRD/32), tb>>>(w_q_b, wqbH, wqbL, QLRD, QBN, QBN, QBN, 0, 0);
    conv_split<<<cblk((long long)HH*NOPED*DLAT/4), 256>>>(w_kc, wkcH, wkcL,
        (long long)HH*NOPED*DLAT/4);                       // [h][d][r] K-contig
    tconv<<<dim3(NOPED/32, DLAT/32, HH), tb>>>(w_vc, wvcH, wvcL, DLAT, NOPED, NOPED, NOPED,
        (long long)DLAT*NOPED, (long long)NOPED*DLAT);     // wvcT [h][v][r]
    tconv<<<dim3(HIDD/32, ATTN/32), tb>>>(w_o, woH, woL, ATTN, HIDD, HIDD, HIDD, 0, 0);

    // --- pipeline ---
    long long n4 = (long long)TT*HIDD/4;
    conv_split<<<cblk(n4), 256>>>(hs, hsH, hsL, n4);

    // 1) [qa | latent] = hs @ [w_q_a | w_kv_a]  (merged, f32 out)
    gemm3<<<dim3(NCOMB/128, 16, 1), 256, DS>>>(hsH, hsL, wcH, wcL, p_qakv, 0, 0,
        NCOMB, HIDD, HIDD, HIDD, NCOMB, 0, 0, 0, 0);
    // 2) rmsnorm of qa slice -> hi/lo
    rmsnorm_split<<<TT, 256>>>(p_qakv, q_a_ln_w, qaH, qaL, QLRD, NCOMB);

    // 3) q = qa @ w_q_b  (f32 for rope_q + hi/lo = Q' nope cols)
    gemm3<<<dim3(QBN/128, 16, 1), 256, DS>>>(qaH, qaL, wqbH, wqbL, p_q, qH, qL,
        QBN, QLRD, QLRD, QLRD, QBN, 0, 0, 0, 0);

    // 5) k_input from latent slice (f32) + hi/lo split
    build_k<<<TT, 256>>>(p_qakv + QLRD, NCOMB, kv_ln_w, p_k);
    n4 = (long long)TT*DQK/4;
    conv_split<<<cblk(n4), 256>>>(p_k, kH, kL, n4);

    // 6) kproj[h] = v_norm @ w_kc[h]^T -> K'[h][s][0:128] hi/lo
    gemm3<<<dim3(1, 16, HH), 256, DS>>>(kH, kL, wkcH, wkcL, 0, kpH, kpL,
        NOPED, DLAT, DQK, DLAT, QKDD,
        0LL, (long long)NOPED*DLAT, (long long)TT*QKDD, 0);
    // 7) K'[h][s][128:192] = roped k_pe (all heads, coalesced)
    pe_fill<<<dim3(TT, HH), 64>>>(p_k, kpH, kpL);

    // 8) Q' pe cols: rope into qH/qL in place
    rope_q<<<dim3(TT, HH), 32>>>(p_q, qH, qL);

    // 9) vwT[h] = wvcT[h] @ v_norm^T  (M=128, N=2048, K=512) -> hi/lo
    gemm3<<<dim3(16, 1, HH), 256, DS>>>(wvcH, wvcL, kH, kL, 0, vwH, vwL,
        TT, DLAT, DLAT, DQK, TT,
        (long long)NOPED*DLAT, 0LL, (long long)NOPED*TT, 0);

    // 10) scores[h] = Q'[h] @ K'[h]^T  (K=192, causal-skip) -> f32
    gemm3<<<dim3(16, 16, HH), 256, DS>>>(qH, qL, kpH, kpL, p_sc, 0, 0,
        TT, QKDD, QBN, QKDD, TT,
        (long long)QKDD, (long long)TT*QKDD, (long long)TT*TT, 1);

    // 11) softmax fused split -> scH/scL
    softmax_split<<<dim3(TT, HH), 256>>>(p_sc, scH, scL);

    // 12) att[:, h*128:(h+1)*128] = probs[h] @ vwT[h]^T  (k-limited) -> hi/lo
    gemm3<<<dim3(1, 16, HH), 256, DS>>>(scH, scL, vwH, vwL, 0, attH, attL,
        NOPED, TT, TT, TT, ATTN,
        (long long)TT*TT, (long long)NOPED*TT, 128LL, 2);

    // 13) out = att @ w_o (f32)
    gemm3<<<dim3(HIDD/128, 16, 1), 256, DS>>>(attH, attL, woH, woL, out, 0, 0,
        HIDD, ATTN, ATTN, ATTN, HIDD, 0, 0, 0, 0);
}

// round 16
// speedup vs baseline: 1.6420x; 1.0134x over previous
#include <cuda_runtime.h>
#include <cuda_bf16.h>
#include <math.h>
#include <stdint.h>

#define TT     2048
#define HIDD   5120
#define ROPED  64
#define NOPED  128
#define HH     32
#define QKDD   192
#define QLRD   1536
#define DQK    576
#define DLAT   512
#define QBN    6144   // H*QKD
#define ATTN   4096   // H*VDIM
#define NCOMB  2176   // QLRD + 640 (padded kv cols)
#define SCALE_F 0.07216878364870323f   // 1/sqrt(192)
#define EPS_F  1e-6f

typedef __nv_bfloat16 bf16;

// ----------------------------- f32 scratch -----------------------------------
__device__ float g_qakv  [(size_t)TT * NCOMB];   // [qa(1536) | latent(576) | pad(64)]
__device__ float g_q     [(size_t)TT * QBN];
__device__ float g_k     [(size_t)TT * DQK];
__device__ float g_scores[(size_t)HH * TT * TT];

// --------------------------- bf16 hi/lo scratch -------------------------------
__device__ bf16 g_hsH [(size_t)TT*HIDD],      g_hsL [(size_t)TT*HIDD];
__device__ bf16 g_wcombH[(size_t)NCOMB*HIDD], g_wcombL[(size_t)NCOMB*HIDD];  // [wqaT | wkvaT(640)]
__device__ bf16 g_qaH [(size_t)TT*QLRD],      g_qaL [(size_t)TT*QLRD];
__device__ bf16 g_wqbT_H[(size_t)QBN*QLRD],   g_wqbT_L[(size_t)QBN*QLRD];
__device__ bf16 g_qH  [(size_t)TT*QBN],       g_qL  [(size_t)TT*QBN];   // Q' (pe roped in place)
__device__ bf16 g_kH  [(size_t)TT*DQK],       g_kL  [(size_t)TT*DQK];
__device__ bf16 g_wkcH[(size_t)HH*NOPED*DLAT], g_wkcL[(size_t)HH*NOPED*DLAT];  // [h][d][r] K-contig
__device__ bf16 g_kpH [(size_t)HH*TT*QKDD],   g_kpL [(size_t)HH*TT*QKDD];     // K' per head [h][s][192]
__device__ bf16 g_scH [(size_t)HH*TT*TT],     g_scL [(size_t)HH*TT*TT];
__device__ bf16 g_wvcT_H[(size_t)HH*NOPED*DLAT], g_wvcT_L[(size_t)HH*NOPED*DLAT]; // [h][v][r]
__device__ bf16 g_vwH [(size_t)HH*NOPED*TT],  g_vwL [(size_t)HH*NOPED*TT];    // vwT [h][v][s]
__device__ bf16 g_attH[(size_t)TT*ATTN],      g_attL[(size_t)TT*ATTN];
__device__ bf16 g_woT_H[(size_t)HIDD*ATTN],   g_woT_L[(size_t)HIDD*ATTN];

// ------------------------------ helpers ---------------------------------------
__device__ __forceinline__ uint32_t smem_u32(const void* p) {
    uint32_t a;
    asm("{ .reg .u64 t; cvta.to.shared.u64 t, %1; cvt.u32.u64 %0, t; }" : "=r"(a) : "l"(p));
    return a;
}

#define SWZ(o) ((o) ^ (((o) >> 3) & 0x70))

__device__ __forceinline__ void ldm_x4(uint32_t* r, uint32_t addr) {
    asm volatile("ldmatrix.sync.aligned.m8n8.x4.shared.b16 {%0,%1,%2,%3}, [%4];"
        : "=r"(r[0]), "=r"(r[1]), "=r"(r[2]), "=r"(r[3]) : "r"(addr));
}

__device__ __forceinline__ void mma16816(float* c, const uint32_t* a, const uint32_t* b) {
    asm volatile("mma.sync.aligned.m16n8k16.row.col.f32.bf16.bf16.f32 "
        "{%0,%1,%2,%3}, {%4,%5,%6,%7}, {%8,%9}, {%0,%1,%2,%3};"
        : "+f"(c[0]), "+f"(c[1]), "+f"(c[2]), "+f"(c[3])
        : "r"(a[0]), "r"(a[1]), "r"(a[2]), "r"(a[3]), "r"(b[0]), "r"(b[1]));
}

__device__ __forceinline__ void cpa16(uint32_t dst, const void* src) {
    asm volatile("cp.async.cg.shared.global [%0], [%1], 16;" :: "r"(dst), "l"(src));
}
#define CP_COMMIT() asm volatile("cp.async.commit_group;" ::: "memory")
#define CP_WAIT0()  asm volatile("cp.async.wait_group 0;" ::: "memory")
#define CP_WAIT1()  asm volatile("cp.async.wait_group 1;" ::: "memory")

// ----------------------- warp-MMA 3-term split GEMM ---------------------------
// C[M,N] = A[M,K] * BT[N,K]^T; A/BT bf16 hi/lo, K-contig. 128x128 CTA tile,
// 3-stage cp.async ring over K-chunks of 64, ONE barrier per chunk.
// mode: 0 none, 1 causal-skip, 2 k-limit (pv). M % 128 == 0.
#define T_A_HI 0
#define T_A_LO 16384
#define T_B_HI 32768
#define T_B_LO 49152
#define STG_SZ 65536
#define GSM_DYN (3*STG_SZ + 1024)

__global__ __launch_bounds__(256)
void gemm3(const bf16* __restrict__ AH, const bf16* __restrict__ AL,
           const bf16* __restrict__ BH, const bf16* __restrict__ BL,
           float* __restrict__ C, bf16* __restrict__ OH, bf16* __restrict__ OL,
           int N, int K, int lda, int ldb, int ldc,
           long long sA, long long sB, long long sC, int mode)
{
    const int bm = blockIdx.y * 128, bn = blockIdx.x * 128;
    if (mode == 1 && bn >= bm + 128) return;
    const int kmax = (mode == 2) ? (bm + 128) : K;
    const int nch  = kmax >> 6;

    AH += (long long)blockIdx.z * sA;  AL += (long long)blockIdx.z * sA;
    BH += (long long)blockIdx.z * sB;  BL += (long long)blockIdx.z * sB;

    extern __shared__ char smraw[];
    char* smem = (char*)(((uintptr_t)smraw + 1023) & ~(uintptr_t)1023);
    const uint32_t sb = smem_u32(smem);

    const int tid  = threadIdx.x;
    const int lane = tid & 31, warp = tid >> 5;
    const int wm = (warp >> 2) * 64;
    const int wn = (warp & 3) * 32;

    float acc[4][4][4];
#pragma unroll
    for (int i = 0; i < 4; i++)
#pragma unroll
        for (int j = 0; j < 4; j++)
#pragma unroll
            for (int q = 0; q < 4; q++) acc[i][j][q] = 0.f;

    const int a_row = (lane & 15);
    const int a_kof = (lane & 16) ? 8 : 0;
    const int b_sel = lane >> 3;
    const int b_row = (lane & 7) + ((b_sel & 2) ? 8 : 0);
    const int b_kof = (b_sel & 1) ? 8 : 0;

    const int l_row = tid >> 3, l_c16 = tid & 7;

#define LOAD_CHUNK(ci)                                                           \
    do {                                                                         \
        const uint32_t _st = sb + (uint32_t)((ci) % 3) * STG_SZ;                 \
        const int _k0 = (ci) << 6;                                               \
        _Pragma("unroll")                                                        \
        for (int it = 0; it < 4; it++) {                                         \
            int row = l_row + it * 32;                                           \
            uint32_t sw = SWZ((uint32_t)(row * 128 + l_c16 * 16));               \
            size_t gA = (size_t)(bm + row) * lda + _k0 + l_c16 * 8;              \
            size_t gB = (size_t)(bn + row) * ldb + _k0 + l_c16 * 8;              \
            cpa16(_st + T_A_HI + sw, AH + gA);                                   \
            cpa16(_st + T_A_LO + sw, AL + gA);                                   \
            cpa16(_st + T_B_HI + sw, BH + gB);                                   \
            cpa16(_st + T_B_LO + sw, BL + gB);                                   \
        }                                                                        \
    } while (0)

    // prologue: chunks 0,1
    LOAD_CHUNK(0); CP_COMMIT();
    if (nch > 1) { LOAD_CHUNK(1); CP_COMMIT(); }

    for (int c = 0; c < nch; c++) {
        if (c + 1 < nch) CP_WAIT1(); else CP_WAIT0();
        __syncthreads();                       // chunk c visible; stage (c-1)%3 free
        if (c + 2 < nch) { LOAD_CHUNK(c + 2); CP_COMMIT(); }   // overlaps MMA below

        const uint32_t st = sb + (uint32_t)(c % 3) * STG_SZ;
#pragma unroll
        for (int kk = 0; kk < 64; kk += 16) {
            uint32_t bh[4][2], bl[4][2];
#pragma unroll
            for (int p = 0; p < 2; p++) {
                uint32_t boff = SWZ((uint32_t)((wn + p * 16 + b_row) * 128 + (kk + b_kof) * 2));
                uint32_t r[4];
                ldm_x4(r, st + T_B_HI + boff);
                bh[2*p][0] = r[0]; bh[2*p][1] = r[1]; bh[2*p+1][0] = r[2]; bh[2*p+1][1] = r[3];
                ldm_x4(r, st + T_B_LO + boff);
                bl[2*p][0] = r[0]; bl[2*p][1] = r[1]; bl[2*p+1][0] = r[2]; bl[2*p+1][1] = r[3];
            }
            uint32_t ah[4][4], al[4][4];
#pragma unroll
            for (int mt = 0; mt < 4; mt++) {
                uint32_t aoff = SWZ((uint32_t)((wm + mt * 16 + a_row) * 128 + (kk + a_kof) * 2));
                ldm_x4(ah[mt], st + T_A_HI + aoff);
                ldm_x4(al[mt], st + T_A_LO + aoff);
            }
#pragma unroll
            for (int mt = 0; mt < 4; mt++)
#pragma unroll
                for (int nt = 0; nt < 4; nt++)
                    mma16816(acc[mt][nt], ah[mt], bh[nt]);
#pragma unroll
            for (int mt = 0; mt < 4; mt++)
#pragma unroll
                for (int nt = 0; nt < 4; nt++)
                    mma16816(acc[mt][nt], ah[mt], bl[nt]);
#pragma unroll
            for (int mt = 0; mt < 4; mt++)
#pragma unroll
                for (int nt = 0; nt < 4; nt++)
                    mma16816(acc[mt][nt], al[mt], bh[nt]);
        }
    }
#undef LOAD_CHUNK

    // ---- epilogue: f32 and/or bf16 hi/lo ----
#pragma unroll
    for (int mt = 0; mt < 4; mt++) {
#pragma unroll
        for (int nt = 0; nt < 4; nt++) {
            int r = bm + wm + mt * 16 + (lane >> 2);
            int c = bn + wn + nt * 8 + 2 * (lane & 3);
            if (c >= N) continue;
            float v0 = acc[mt][nt][0], v1 = acc[mt][nt][1];
            float v2 = acc[mt][nt][2], v3 = acc[mt][nt][3];
            if (C) {
                float* Cz = C + (long long)blockIdx.z * sC;
                *(float2*)&Cz[(size_t)r * ldc + c]       = make_float2(v0, v1);
                *(float2*)&Cz[(size_t)(r + 8) * ldc + c] = make_float2(v2, v3);
            }
            if (OH) {
                bf16* Hz = OH + (long long)blockIdx.z * sC;
                bf16* Lz = OL + (long long)blockIdx.z * sC;
                bf16 h0 = __float2bfloat16(v0), h1 = __float2bfloat16(v1);
                bf16 h2 = __float2bfloat16(v2), h3 = __float2bfloat16(v3);
                *(__nv_bfloat162*)&Hz[(size_t)r * ldc + c] = __nv_bfloat162(h0, h1);
                *(__nv_bfloat162*)&Hz[(size_t)(r + 8) * ldc + c] = __nv_bfloat162(h2, h3);
                *(__nv_bfloat162*)&Lz[(size_t)r * ldc + c] =
                    __nv_bfloat162(__float2bfloat16(v0 - __bfloat162float(h0)),
                                   __float2bfloat16(v1 - __bfloat162float(h1)));
                *(__nv_bfloat162*)&Lz[(size_t)(r + 8) * ldc + c] =
                    __nv_bfloat162(__float2bfloat16(v2 - __bfloat162float(h2)),
                                   __float2bfloat16(v3 - __bfloat162float(h3)));
            }
        }
    }
}

// --------------------- elementwise f32 -> bf16 hi/lo ---------------------------
__global__ void conv_split(const float* __restrict__ x, bf16* __restrict__ hi,
                           bf16* __restrict__ lo, long long n4)
{
    long long i = (long long)blockIdx.x * blockDim.x + threadIdx.x;
    long long stride = (long long)gridDim.x * blockDim.x;
    for (; i < n4; i += stride) {
        float4 v = ((const float4*)x)[i];
        bf16 hx = __float2bfloat16(v.x), hy = __float2bfloat16(v.y);
        bf16 hz = __float2bfloat16(v.z), hw = __float2bfloat16(v.w);
        __nv_bfloat162* H = (__nv_bfloat162*)hi;
        __nv_bfloat162* L = (__nv_bfloat162*)lo;
        H[2*i]   = __nv_bfloat162(hx, hy);
        H[2*i+1] = __nv_bfloat162(hz, hw);
        L[2*i]   = __nv_bfloat162(__float2bfloat16(v.x - __bfloat162float(hx)),
                                  __float2bfloat16(v.y - __bfloat162float(hy)));
        L[2*i+1] = __nv_bfloat162(__float2bfloat16(v.z - __bfloat162float(hz)),
                                  __float2bfloat16(v.w - __bfloat162float(hw)));
    }
}

// ------------- transpose + split: src[R][C] f32 (lda) -> dst[CP][R] bf16 -------
__global__ void tconv(const float* __restrict__ src, bf16* __restrict__ dh,
                      bf16* __restrict__ dl, int R, int C, int CP, int lda,
                      long long zs, long long zd)
{
    src += (long long)blockIdx.z * zs;
    dh  += (long long)blockIdx.z * zd;
    dl  += (long long)blockIdx.z * zd;
    __shared__ float t[32][33];
    int c  = blockIdx.x * 32 + threadIdx.x;
    int r0 = blockIdx.y * 32;
#pragma unroll
    for (int i = 0; i < 32; i += 8) {
        int r = r0 + threadIdx.y + i;
        t[threadIdx.y + i][threadIdx.x] = (c < C && r < R) ? src[(size_t)r * lda + c] : 0.f;
    }
    __syncthreads();
    int ro = blockIdx.x * 32;
    int co = r0 + threadIdx.x;
#pragma unroll
    for (int i = 0; i < 32; i += 8) {
        int rr = ro + threadIdx.y + i;
        if (rr < CP && co < R) {
            float v = t[threadIdx.x][threadIdx.y + i];
            bf16 h = __float2bfloat16(v);
            dh[(size_t)rr * R + co] = h;
            dl[(size_t)rr * R + co] = __float2bfloat16(v - __bfloat162float(h));
        }
    }
}

// ------------------------- block reduce helper -------------------------------
__device__ __forceinline__ float blockReduce(float v, bool isMax)
{
    __shared__ float sm[9];
    int lane = threadIdx.x & 31, w = threadIdx.x >> 5;
#pragma unroll
    for (int o = 16; o > 0; o >>= 1) {
        float ov = __shfl_xor_sync(0xffffffffu, v, o);
        v = isMax ? fmaxf(v, ov) : v + ov;
    }
    if (lane == 0) sm[w] = v;
    __syncthreads();
    if (w == 0) {
        int nw = blockDim.x >> 5;
        v = (lane < nw) ? sm[lane] : (isMax ? -INFINITY : 0.f);
#pragma unroll
        for (int o = 4; o > 0; o >>= 1) {
            float ov = __shfl_xor_sync(0xffffffffu, v, o);
            v = isMax ? fmaxf(v, ov) : v + ov;
        }
        if (lane == 0) sm[8] = v;
    }
    __syncthreads();
    return sm[8];
}

// ---- rmsnorm rows (row stride ld), fused split output (hi/lo bf16) -----------
__global__ void rmsnorm_split(const float* __restrict__ x, const float* __restrict__ w,
                              bf16* __restrict__ oh, bf16* __restrict__ ol, int n, int ld)
{
    const float* row = x + (size_t)blockIdx.x * ld;
    bf16* rh = oh + (size_t)blockIdx.x * n;
    bf16* rl = ol + (size_t)blockIdx.x * n;
    float s = 0.f;
    for (int i = threadIdx.x; i < n; i += blockDim.x) { float v = row[i]; s += v * v; }
    s = blockReduce(s, false);
    float sc = rsqrtf(s / (float)n + EPS_F);
    for (int i = threadIdx.x; i < n; i += blockDim.x) {
        float v = row[i] * sc * w[i];
        bf16 h = __float2bfloat16(v);
        rh[i] = h;
        rl[i] = __float2bfloat16(v - __bfloat162float(h));
    }
}

__device__ __forceinline__ void rope_cs(int posv, int j, float& c, float& s)
{
    float e    = (float)(2 * j) * (1.0f / 64.0f);
    float invf = 1.0f / powf(10000.0f, e);
    float freq = (float)posv * invf;
    double fd  = (double)freq;
    double q   = floor(fd * 0.15915494309189535);
    double r   = fd - q * 6.283185307179586;
    float  rf  = (float)r;
    c = cosf(rf); s = sinf(rf);
}

// ------- build k_input from latent slice (row stride ldlat) -------------------
__global__ void build_k(const float* __restrict__ lat, int ldlat,
                        const float* __restrict__ w, float* __restrict__ k)
{
    int t = blockIdx.x;
    const float* L = lat + (size_t)t * ldlat;
    float*       K = k   + (size_t)t * DQK;
    float ssq = 0.f;
    for (int i = threadIdx.x; i < DLAT; i += blockDim.x) { float v = L[i]; ssq += v * v; }
    ssq = blockReduce(ssq, false);
    float sc = rsqrtf(ssq / (float)DLAT + EPS_F);
    for (int i = threadIdx.x; i < DLAT; i += blockDim.x) K[i] = L[i] * sc * w[i];
    if (threadIdx.x < 32) {
        int j = threadIdx.x;
        float c, s;
        rope_cs(t, j, c, s);
        float x1 = L[DLAT + 2*j], x2 = L[DLAT + 2*j + 1];
        K[DLAT + 2*j]     = x1 * c - x2 * s;
        K[DLAT + 2*j + 1] = x2 * c + x1 * s;
    }
}

// ---- replicate roped k_pe into every head's K' rows (coalesced) --------------
__global__ void pe_fill(const float* __restrict__ k, bf16* __restrict__ kpH,
                        bf16* __restrict__ kpL)
{
    int s = blockIdx.x, hh = blockIdx.y, j = threadIdx.x;   // 64 threads
    float v = k[(size_t)s * DQK + DLAT + j];
    bf16 h = __float2bfloat16(v);
    bf16 l = __float2bfloat16(v - __bfloat162float(h));
    size_t o = ((size_t)hh * TT + s) * QKDD + NOPED + j;
    kpH[o] = h;
    kpL[o] = l;
}

// ------------- q-side rope, writing into qH/qL pe slots in place --------------
__global__ void rope_q(const float* __restrict__ q, bf16* __restrict__ qh,
                       bf16* __restrict__ ql)
{
    int t = blockIdx.x, h = blockIdx.y, j = threadIdx.x;
    const float* src = q + (size_t)t * QBN + h * QKDD + NOPED;
    size_t off = (size_t)t * QBN + h * QKDD + NOPED;
    float c, s;
    rope_cs(t, j, c, s);
    float x1 = src[2*j], x2 = src[2*j + 1];
    float o1 = x1 * c - x2 * s;
    float o2 = x2 * c + x1 * s;
    bf16 h1 = __float2bfloat16(o1), h2 = __float2bfloat16(o2);
    qh[off + 2*j]     = h1;
    qh[off + 2*j + 1] = h2;
    ql[off + 2*j]     = __float2bfloat16(o1 - __bfloat162float(h1));
    ql[off + 2*j + 1] = __float2bfloat16(o2 - __bfloat162float(h2));
}

// ------- causal softmax, smem row cache, single exp pass, split output --------
__global__ void softmax_split(const float* __restrict__ scores,
                              bf16* __restrict__ SH, bf16* __restrict__ SL)
{
    __shared__ float sp[TT];
    int t = blockIdx.x, h = blockIdx.y;
    const float* row = scores + ((size_t)h * TT + t) * TT;
    bf16* oh = SH + ((size_t)h * TT + t) * TT;
    bf16* ol = SL + ((size_t)h * TT + t) * TT;
    int n = t + 1;
    int nlim = ((t >> 7) + 1) << 7;   // 128-aligned extent read by PV gemm

    float m = -INFINITY;
    for (int i = threadIdx.x; i < n; i += blockDim.x) {
        float v = row[i] * SCALE_F;
        sp[i] = v;
        m = fmaxf(m, v);
    }
    m = blockReduce(m, true);

    float s = 0.f;
    for (int i = threadIdx.x; i < n; i += blockDim.x) {
        float p = __expf(sp[i] - m);
        sp[i] = p;
        s += p;
    }
    s = blockReduce(s, false);
    float inv = 1.f / s;

    for (int i = threadIdx.x; i < nlim; i += blockDim.x) {
        float p = (i < n) ? sp[i] * inv : 0.f;
        bf16 hp = __float2bfloat16(p);
        oh[i] = hp;
        ol[i] = __float2bfloat16(p - __bfloat162float(hp));
    }
}

// ------------------------------- launch --------------------------------------
static inline int cblk(long long n4) {
    long long b = (n4 + 255) / 256;
    return (int)(b > 262144 ? 262144 : b);
}

extern "C" void kernel_launch(void* const* d_in, const int* in_sizes, int n_in,
                              void* d_out, int out_size)
{
    const float* hs       = (const float*)d_in[0];
    const float* w_q_a    = (const float*)d_in[2];
    const float* q_a_ln_w = (const float*)d_in[3];
    const float* w_q_b    = (const float*)d_in[4];
    const float* w_kv_a   = (const float*)d_in[5];
    const float* kv_ln_w  = (const float*)d_in[6];
    const float* w_kc     = (const float*)d_in[7];
    const float* w_vc     = (const float*)d_in[8];
    const float* w_o      = (const float*)d_in[9];
    float*       out      = (float*)d_out;

    float *p_qakv, *p_q, *p_k, *p_sc;
    cudaGetSymbolAddress((void**)&p_qakv, g_qakv);
    cudaGetSymbolAddress((void**)&p_q,   g_q);
    cudaGetSymbolAddress((void**)&p_k,   g_k);
    cudaGetSymbolAddress((void**)&p_sc,  g_scores);

    bf16 *hsH,*hsL,*wcH,*wcL,*qaH,*qaL,*wqbH,*wqbL,*qH,*qL,*kH,*kL;
    bf16 *wkcH,*wkcL,*kpH,*kpL,*scH,*scL,*wvcH,*wvcL,*vwH,*vwL,*attH,*attL,*woH,*woL;
    cudaGetSymbolAddress((void**)&hsH, g_hsH);   cudaGetSymbolAddress((void**)&hsL, g_hsL);
    cudaGetSymbolAddress((void**)&wcH, g_wcombH); cudaGetSymbolAddress((void**)&wcL, g_wcombL);
    cudaGetSymbolAddress((void**)&qaH, g_qaH);   cudaGetSymbolAddress((void**)&qaL, g_qaL);
    cudaGetSymbolAddress((void**)&wqbH, g_wqbT_H); cudaGetSymbolAddress((void**)&wqbL, g_wqbT_L);
    cudaGetSymbolAddress((void**)&qH, g_qH);     cudaGetSymbolAddress((void**)&qL, g_qL);
    cudaGetSymbolAddress((void**)&kH, g_kH);     cudaGetSymbolAddress((void**)&kL, g_kL);
    cudaGetSymbolAddress((void**)&wkcH, g_wkcH); cudaGetSymbolAddress((void**)&wkcL, g_wkcL);
    cudaGetSymbolAddress((void**)&kpH, g_kpH);   cudaGetSymbolAddress((void**)&kpL, g_kpL);
    cudaGetSymbolAddress((void**)&scH, g_scH);   cudaGetSymbolAddress((void**)&scL, g_scL);
    cudaGetSymbolAddress((void**)&wvcH, g_wvcT_H); cudaGetSymbolAddress((void**)&wvcL, g_wvcT_L);
    cudaGetSymbolAddress((void**)&vwH, g_vwH);   cudaGetSymbolAddress((void**)&vwL, g_vwL);
    cudaGetSymbolAddress((void**)&attH, g_attH); cudaGetSymbolAddress((void**)&attL, g_attL);
    cudaGetSymbolAddress((void**)&woH, g_woT_H); cudaGetSymbolAddress((void**)&woL, g_woT_L);

    cudaFuncSetAttribute(gemm3, cudaFuncAttributeMaxDynamicSharedMemorySize, GSM_DYN);
    const int DS = GSM_DYN;
    dim3 tb(32, 8);

    // --- preprocess weights ---
    tconv<<<dim3(QLRD/32, HIDD/32), tb>>>(w_q_a, wcH, wcL, HIDD, QLRD, QLRD, QLRD, 0, 0);
    tconv<<<dim3(640/32,  HIDD/32), tb>>>(w_kv_a,
        wcH + (size_t)QLRD*HIDD, wcL + (size_t)QLRD*HIDD, HIDD, DQK, 640, DQK, 0, 0);
    tconv<<<dim3(QBN/32,  QLRD/32), tb>>>(w_q_b, wqbH, wqbL, QLRD, QBN, QBN, QBN, 0, 0);
    conv_split<<<cblk((long long)HH*NOPED*DLAT/4), 256>>>(w_kc, wkcH, wkcL,
        (long long)HH*NOPED*DLAT/4);                       // [h][d][r] K-contig
    tconv<<<dim3(NOPED/32, DLAT/32, HH), tb>>>(w_vc, wvcH, wvcL, DLAT, NOPED, NOPED, NOPED,
        (long long)DLAT*NOPED, (long long)NOPED*DLAT);     // wvcT [h][v][r]
    tconv<<<dim3(HIDD/32, ATTN/32), tb>>>(w_o, woH, woL, ATTN, HIDD, HIDD, HIDD, 0, 0);

    // --- pipeline ---
    long long n4 = (long long)TT*HIDD/4;
    conv_split<<<cblk(n4), 256>>>(hs, hsH, hsL, n4);

    // 1) [qa | latent] = hs @ [w_q_a | w_kv_a]  (merged, f32 out)
    gemm3<<<dim3(NCOMB/128, 16, 1), 256, DS>>>(hsH, hsL, wcH, wcL, p_qakv, 0, 0,
        NCOMB, HIDD, HIDD, HIDD, NCOMB, 0, 0, 0, 0);
    // 2) rmsnorm of qa slice -> hi/lo
    rmsnorm_split<<<TT, 256>>>(p_qakv, q_a_ln_w, qaH, qaL, QLRD, NCOMB);

    // 3) q = qa @ w_q_b  (f32 for rope_q + hi/lo = Q' nope cols)
    gemm3<<<dim3(QBN/128, 16, 1), 256, DS>>>(qaH, qaL, wqbH, wqbL, p_q, qH, qL,
        QBN, QLRD, QLRD, QLRD, QBN, 0, 0, 0, 0);

    // 5) k_input from latent slice (f32) + hi/lo split
    build_k<<<TT, 256>>>(p_qakv + QLRD, NCOMB, kv_ln_w, p_k);
    n4 = (long long)TT*DQK/4;
    conv_split<<<cblk(n4), 256>>>(p_k, kH, kL, n4);

    // 6) kproj[h] = v_norm @ w_kc[h]^T -> K'[h][s][0:128] hi/lo
    gemm3<<<dim3(1, 16, HH), 256, DS>>>(kH, kL, wkcH, wkcL, 0, kpH, kpL,
        NOPED, DLAT, DQK, DLAT, QKDD,
        0LL, (long long)NOPED*DLAT, (long long)TT*QKDD, 0);
    // 7) K'[h][s][128:192] = roped k_pe (all heads, coalesced)
    pe_fill<<<dim3(TT, HH), 64>>>(p_k, kpH, kpL);

    // 8) Q' pe cols: rope into qH/qL in place
    rope_q<<<dim3(TT, HH), 32>>>(p_q, qH, qL);

    // 9) vwT[h] = wvcT[h] @ v_norm^T  (M=128, N=2048, K=512) -> hi/lo
    gemm3<<<dim3(16, 1, HH), 256, DS>>>(wvcH, wvcL, kH, kL, 0, vwH, vwL,
        TT, DLAT, DLAT, DQK, TT,
        (long long)NOPED*DLAT, 0LL, (long long)NOPED*TT, 0);

    // 10) scores[h] = Q'[h] @ K'[h]^T  (K=192, causal-skip) -> f32
    gemm3<<<dim3(16, 16, HH), 256, DS>>>(qH, qL, kpH, kpL, p_sc, 0, 0,
        TT, QKDD, QBN, QKDD, TT,
        (long long)QKDD, (long long)TT*QKDD, (long long)TT*TT, 1);

    // 11) softmax fused split -> scH/scL
    softmax_split<<<dim3(TT, HH), 256>>>(p_sc, scH, scL);

    // 12) att[:, h*128:(h+1)*128] = probs[h] @ vwT[h]^T  (k-limited) -> hi/lo
    gemm3<<<dim3(1, 16, HH), 256, DS>>>(scH, scL, vwH, vwL, 0, attH, attL,
        NOPED, TT, TT, TT, ATTN,
        (long long)TT*TT, (long long)NOPED*TT, 128LL, 2);

    // 13) out = att @ w_o (f32)
    gemm3<<<dim3(HIDD/128, 16, 1), 256, DS>>>(attH, attL, woH, woL, out, 0, 0,
        HIDD, ATTN, ATTN, ATTN, HIDD, 0, 0, 0, 0);
}